// round 1
// baseline (speedup 1.0000x reference)
#include <cuda_runtime.h>
#include <math.h>

// Problem constants (fixed by the dataset)
#define BB   2
#define DD   256
#define THW  8192      // T*H*W = 8*32*32
#define NN   16384     // BB*THW
#define KK   8192

// -------- device scratch (no allocations allowed) --------
__device__ float g_H1[KK * DD];     // gelu(emb @ w1^T)
__device__ float g_CB[KK * DD];     // codebook
__device__ float g_cbsq[KK];        // ||cb_k||^2
__device__ float g_csum[DD];        // column sums of CB
__device__ float g_zcol[DD];        // column sums of z_flat
__device__ float g_scal[3];         // 0: sum z^2, 1: sum cb^2, 2: loss acc
__device__ int   g_idx[NN];
__device__ int   g_counts[KK];

// -------- helpers --------
__device__ __forceinline__ float blockReduceSum(float v) {
    __shared__ float sh[32];
    int lane = threadIdx.x & 31, w = threadIdx.x >> 5;
    #pragma unroll
    for (int o = 16; o; o >>= 1) v += __shfl_xor_sync(0xffffffffu, v, o);
    if (lane == 0) sh[w] = v;
    __syncthreads();
    v = (threadIdx.x < (blockDim.x >> 5)) ? sh[threadIdx.x] : 0.f;
    if (w == 0) {
        #pragma unroll
        for (int o = 16; o; o >>= 1) v += __shfl_xor_sync(0xffffffffu, v, o);
    }
    __syncthreads();
    return v;  // valid in thread 0
}

// -------- init: zero accumulators --------
__global__ void k_init() {
    int t = blockIdx.x * blockDim.x + threadIdx.x;
    if (t < KK) g_counts[t] = 0;
    if (t < DD) { g_csum[t] = 0.f; g_zcol[t] = 0.f; }
    if (t < 3)  g_scal[t] = 0.f;
}

// -------- codebook GEMMs: C[M,256] = op(A[M,256] @ B[256,256]^T) --------
// mode 0: A=emb (param), C=g_H1, apply exact GELU.  mode 1: A=g_H1, C=g_CB.
__global__ void __launch_bounds__(256) gemm_cb(const float* __restrict__ Aext,
                                               const float* __restrict__ Bext,
                                               int mode) {
    const float* A = mode ? g_H1 : Aext;
    float*       C = mode ? g_CB : g_H1;
    const float* Bm = Bext;

    __shared__ __align__(16) float As[16][64];
    __shared__ __align__(16) float Bs[16][64];

    int m0 = blockIdx.y * 64;
    int n0 = blockIdx.x * 64;
    int tid = threadIdx.x;
    int ty = tid >> 4, tx = tid & 15;
    int lr = tid >> 2, lseg = tid & 3;

    float acc[4][4];
    #pragma unroll
    for (int i = 0; i < 4; i++)
        #pragma unroll
        for (int j = 0; j < 4; j++) acc[i][j] = 0.f;

    for (int d0 = 0; d0 < 256; d0 += 16) {
        __syncthreads();
        {
            float4 va = *(const float4*)(A + (size_t)(m0 + lr) * 256 + d0 + lseg * 4);
            As[lseg * 4 + 0][lr] = va.x; As[lseg * 4 + 1][lr] = va.y;
            As[lseg * 4 + 2][lr] = va.z; As[lseg * 4 + 3][lr] = va.w;
            float4 vb = *(const float4*)(Bm + (size_t)(n0 + lr) * 256 + d0 + lseg * 4);
            Bs[lseg * 4 + 0][lr] = vb.x; Bs[lseg * 4 + 1][lr] = vb.y;
            Bs[lseg * 4 + 2][lr] = vb.z; Bs[lseg * 4 + 3][lr] = vb.w;
        }
        __syncthreads();
        #pragma unroll
        for (int kk = 0; kk < 16; kk++) {
            float4 a = *(float4*)&As[kk][ty * 4];
            float4 b = *(float4*)&Bs[kk][tx * 4];
            float ar[4] = {a.x, a.y, a.z, a.w};
            float br[4] = {b.x, b.y, b.z, b.w};
            #pragma unroll
            for (int i = 0; i < 4; i++)
                #pragma unroll
                for (int j = 0; j < 4; j++) acc[i][j] += ar[i] * br[j];
        }
    }
    #pragma unroll
    for (int i = 0; i < 4; i++)
        #pragma unroll
        for (int j = 0; j < 4; j++) {
            float x = acc[i][j];
            if (mode == 0) x = 0.5f * x * (1.f + erff(x * 0.70710678118654752f));
            C[(size_t)(m0 + ty * 4 + i) * 256 + n0 + tx * 4 + j] = x;
        }
}

// -------- codebook row stats: ||cb_k||^2, column sums --------
__global__ void __launch_bounds__(256) cb_stats() {
    __shared__ float colp[256];
    int tid = threadIdx.x;
    colp[tid] = 0.f;
    __syncthreads();
    int w = tid >> 5, l = tid & 31;
    int row = blockIdx.x * 8 + w;
    const float4* p = (const float4*)(g_CB + (size_t)row * 256) + l * 2;
    float4 v0 = p[0], v1 = p[1];
    float sq = v0.x * v0.x + v0.y * v0.y + v0.z * v0.z + v0.w * v0.w
             + v1.x * v1.x + v1.y * v1.y + v1.z * v1.z + v1.w * v1.w;
    float s = sq;
    #pragma unroll
    for (int o = 16; o; o >>= 1) s += __shfl_xor_sync(0xffffffffu, s, o);
    if (l == 0) { g_cbsq[row] = s; atomicAdd(&g_scal[1], s); }
    int dbase = l * 8;
    atomicAdd(&colp[dbase + 0], v0.x); atomicAdd(&colp[dbase + 1], v0.y);
    atomicAdd(&colp[dbase + 2], v0.z); atomicAdd(&colp[dbase + 3], v0.w);
    atomicAdd(&colp[dbase + 4], v1.x); atomicAdd(&colp[dbase + 5], v1.y);
    atomicAdd(&colp[dbase + 6], v1.z); atomicAdd(&colp[dbase + 7], v1.w);
    __syncthreads();
    atomicAdd(&g_csum[tid], colp[tid]);
}

// -------- z stats: sum z^2 and per-d column sums --------
__global__ void __launch_bounds__(256) z_stats(const float* __restrict__ z) {
    int blk = blockIdx.x;              // b*256 + d
    const float4* p = (const float4*)(z + (size_t)blk * THW);
    float s = 0.f, s2 = 0.f;
    #pragma unroll
    for (int j = 0; j < 8; j++) {
        float4 v = p[threadIdx.x + j * 256];
        s  += v.x + v.y + v.z + v.w;
        s2 += v.x * v.x + v.y * v.y + v.z * v.z + v.w * v.w;
    }
    float ts = blockReduceSum(s);
    float ts2 = blockReduceSum(s2);
    if (threadIdx.x == 0) {
        atomicAdd(&g_zcol[blk & 255], ts);
        atomicAdd(&g_scal[0], ts2);
    }
}

// -------- main fused distance + argmin kernel --------
// Grid: 256 blocks, each handles 64 consecutive tokens vs all 8192 codes.
__global__ void __launch_bounds__(256, 2) dist_argmin(const float* __restrict__ z) {
    __shared__ __align__(16) float As[16][64];    // z tile:  [kchunk][token]
    __shared__ __align__(16) float Bs[16][256];   // cb tile: [kchunk][code]
    __shared__ float cbsq_s[256];

    int n0 = blockIdx.x * 64;
    int b = n0 >> 13;
    int s0 = n0 & (THW - 1);
    const float* zbase = z + (size_t)b * (DD * THW) + s0;   // [d*THW + m]

    int tid = threadIdx.x;
    int ty = tid >> 5;        // 0..7  -> token group of 8
    int tx = tid & 31;        // 0..31 -> code group of 8

    float bestv[8];
    int   besti[8];
    #pragma unroll
    for (int r = 0; r < 8; r++) { bestv[r] = 3.4e38f; besti[r] = 0; }

    int a_dl = tid >> 4, a_m4 = (tid & 15) * 4;

    for (int chunk = 0; chunk < 32; chunk++) {
        int c0 = chunk * 256;
        cbsq_s[tid] = g_cbsq[c0 + tid];
        float acc[8][8];
        #pragma unroll
        for (int r = 0; r < 8; r++)
            #pragma unroll
            for (int c = 0; c < 8; c++) acc[r][c] = 0.f;

        for (int d0 = 0; d0 < 256; d0 += 16) {
            __syncthreads();
            // A tile: 64 tokens x 16 dims (coalesced float4 loads along token dim)
            {
                float4 v = *(const float4*)(zbase + (size_t)(d0 + a_dl) * THW + a_m4);
                *(float4*)&As[a_dl][a_m4] = v;
            }
            // B tile: 256 codes x 16 dims (each thread one code row, transposed store)
            {
                const float4* src = (const float4*)(g_CB + (size_t)(c0 + tid) * 256 + d0);
                #pragma unroll
                for (int j = 0; j < 4; j++) {
                    float4 v = src[j];
                    Bs[j * 4 + 0][tid] = v.x; Bs[j * 4 + 1][tid] = v.y;
                    Bs[j * 4 + 2][tid] = v.z; Bs[j * 4 + 3][tid] = v.w;
                }
            }
            __syncthreads();
            #pragma unroll
            for (int kk = 0; kk < 16; kk++) {
                float a[8], bb[8];
                *(float4*)&a[0]  = *(float4*)&As[kk][ty * 8];
                *(float4*)&a[4]  = *(float4*)&As[kk][ty * 8 + 4];
                *(float4*)&bb[0] = *(float4*)&Bs[kk][tx * 8];
                *(float4*)&bb[4] = *(float4*)&Bs[kk][tx * 8 + 4];
                #pragma unroll
                for (int r = 0; r < 8; r++)
                    #pragma unroll
                    for (int c = 0; c < 8; c++) acc[r][c] += a[r] * bb[c];
            }
        }
        // score = ||cb||^2 - 2 z.cb   (||z||^2 constant per row -> same argmin)
        #pragma unroll
        for (int r = 0; r < 8; r++) {
            #pragma unroll
            for (int c = 0; c < 8; c++) {
                float sc = cbsq_s[tx * 8 + c] - 2.f * acc[r][c];
                int gi = c0 + tx * 8 + c;
                if (sc < bestv[r]) { bestv[r] = sc; besti[r] = gi; }
            }
        }
        __syncthreads();
    }

    // reduce 32 candidates per token (reuse Bs storage)
    float* rv = &Bs[0][0];                 // 2048 floats
    int*   ri = (int*)(&Bs[0][0]) + 2048;  // 2048 ints
    #pragma unroll
    for (int r = 0; r < 8; r++) {
        int row = ty * 8 + r;
        rv[row * 32 + tx] = bestv[r];
        ri[row * 32 + tx] = besti[r];
    }
    __syncthreads();
    if (tid < 64) {
        float bv = rv[tid * 32];
        int   bi = ri[tid * 32];
        #pragma unroll 4
        for (int j = 1; j < 32; j++) {
            float v = rv[tid * 32 + j];
            int   i = ri[tid * 32 + j];
            if (v < bv || (v == bv && i < bi)) { bv = v; bi = i; }
        }
        g_idx[n0 + tid] = bi;
        atomicAdd(&g_counts[bi], 1);
    }
}

// -------- gather z_q (channels-first) + loss accumulation --------
__global__ void __launch_bounds__(256) gather_loss(const float* __restrict__ z,
                                                   float* __restrict__ out) {
    unsigned int e = blockIdx.x * 256u + threadIdx.x;   // < 4194304
    int b = e >> 21;
    int d = (e >> 13) & 255;
    int s = e & (THW - 1);
    int n = (b << 13) | s;
    int id = g_idx[n];
    float q = g_CB[(size_t)id * 256 + d];
    out[e] = q;
    float diff = q - z[e];
    float ls = blockReduceSum(diff * diff);
    if (threadIdx.x == 0) atomicAdd(&g_scal[2], ls);
}

// -------- finalize scalars --------
__global__ void __launch_bounds__(256) finalize(float* __restrict__ out) {
    // perplexity
    float ps = 0.f;
    for (int k = threadIdx.x; k < KK; k += 256) {
        float e = (float)g_counts[k] * (1.f / (float)NN);
        ps += e * logf(e + 1e-10f);
    }
    float ent = blockReduceSum(ps);
    // z_bar . cb_bar
    float dp = (g_zcol[threadIdx.x] * (1.f / (float)NN)) *
               (g_csum[threadIdx.x] * (1.f / (float)KK));
    float dot = blockReduceSum(dp);
    if (threadIdx.x == 0) {
        float loss = 1.25f * g_scal[2] / (float)((size_t)NN * DD);
        float perp = expf(-ent);
        float meand = g_scal[0] / (float)NN + g_scal[1] / (float)KK - 2.f * dot;
        out[4194304] = loss;
        out[4194305] = perp;
        out[4194306] = meand;
    }
}

extern "C" void kernel_launch(void* const* d_in, const int* in_sizes, int n_in,
                              void* d_out, int out_size) {
    const float* z   = (const float*)d_in[0];
    const float* emb = (const float*)d_in[1];
    const float* w1  = (const float*)d_in[2];
    const float* w2  = (const float*)d_in[3];
    float* out = (float*)d_out;

    k_init<<<32, 256>>>();
    gemm_cb<<<dim3(4, 128), 256>>>(emb, w1, 0);   // H1 = gelu(emb @ w1^T)
    gemm_cb<<<dim3(4, 128), 256>>>(emb, w2, 1);   // CB = H1 @ w2^T
    cb_stats<<<1024, 256>>>();
    z_stats<<<512, 256>>>(z);
    dist_argmin<<<256, 256>>>(z);
    gather_loss<<<16384, 256>>>(z, out);
    finalize<<<1, 256>>>(out);
}

// round 3
// speedup vs baseline: 3.3966x; 3.3966x over previous
#include <cuda_runtime.h>
#include <cuda_bf16.h>
#include <math.h>
#include <stdint.h>

// Problem constants (fixed by the dataset)
#define BB   2
#define DD   256
#define THW  8192
#define NN   16384
#define KK   8192

// -------- device scratch (no allocations allowed) --------
__device__ float g_H1[KK * DD];
__device__ float g_CB[KK * DD];
__device__ __nv_bfloat16 g_CBhi[KK * DD];
__device__ __nv_bfloat16 g_CBlo[KK * DD];
__device__ __nv_bfloat16 g_Zhi[NN * DD];
__device__ __nv_bfloat16 g_Zlo[NN * DD];
__device__ float g_cbsq[KK];
__device__ float g_csum[DD];
__device__ float g_zcol[DD];
__device__ float g_scal[3];
__device__ unsigned long long g_best[NN];
__device__ int   g_counts[KK];

// ================= PTX helpers (base sm_103-safe: sm_80-era ops only) =====
__device__ __forceinline__ uint32_t smem_to_u32(const void* p) {
    uint32_t a;
    asm("{ .reg .u64 t; cvta.to.shared.u64 t, %1; cvt.u32.u64 %0, t; }" : "=r"(a) : "l"(p));
    return a;
}
__device__ __forceinline__ void cpa16(uint32_t saddr, const void* g) {
    asm volatile("cp.async.cg.shared.global [%0], [%1], 16;" :: "r"(saddr), "l"(g) : "memory");
}
#define CP_COMMIT() asm volatile("cp.async.commit_group;" ::: "memory")
#define CP_WAIT1()  asm volatile("cp.async.wait_group 1;" ::: "memory")

__device__ __forceinline__ void ldsm4(uint32_t (&r)[4], uint32_t addr) {
    asm volatile("ldmatrix.sync.aligned.m8n8.x4.shared.b16 {%0,%1,%2,%3}, [%4];"
        : "=r"(r[0]), "=r"(r[1]), "=r"(r[2]), "=r"(r[3]) : "r"(addr));
}
__device__ __forceinline__ void mma16816(float (&d)[4], const uint32_t (&a)[4],
                                         uint32_t b0, uint32_t b1) {
    asm volatile("mma.sync.aligned.m16n8k16.row.col.f32.bf16.bf16.f32 "
        "{%0,%1,%2,%3}, {%4,%5,%6,%7}, {%8,%9}, {%0,%1,%2,%3};"
        : "+f"(d[0]), "+f"(d[1]), "+f"(d[2]), "+f"(d[3])
        : "r"(a[0]), "r"(a[1]), "r"(a[2]), "r"(a[3]), "r"(b0), "r"(b1));
}

// -------- helpers --------
__device__ __forceinline__ float blockReduceSum(float v) {
    __shared__ float sh[32];
    int lane = threadIdx.x & 31, w = threadIdx.x >> 5;
    #pragma unroll
    for (int o = 16; o; o >>= 1) v += __shfl_xor_sync(0xffffffffu, v, o);
    if (lane == 0) sh[w] = v;
    __syncthreads();
    v = (threadIdx.x < (blockDim.x >> 5)) ? sh[threadIdx.x] : 0.f;
    if (w == 0) {
        #pragma unroll
        for (int o = 16; o; o >>= 1) v += __shfl_xor_sync(0xffffffffu, v, o);
    }
    __syncthreads();
    return v;
}

__global__ void k_init() {
    int t = blockIdx.x * blockDim.x + threadIdx.x;
    if (t < NN) g_best[t] = ~0ull;
    if (t < KK) g_counts[t] = 0;
    if (t < DD) { g_csum[t] = 0.f; g_zcol[t] = 0.f; }
    if (t < 3)  g_scal[t] = 0.f;
}

// -------- codebook GEMMs (SIMT, small: 2 x 8192x256x256) --------
__global__ void __launch_bounds__(256) gemm_cb(const float* __restrict__ Aext,
                                               const float* __restrict__ Bext,
                                               int mode) {
    const float* A = mode ? g_H1 : Aext;
    float*       C = mode ? g_CB : g_H1;
    const float* Bm = Bext;
    __shared__ __align__(16) float As[16][64];
    __shared__ __align__(16) float Bs[16][64];
    int m0 = blockIdx.y * 64, n0 = blockIdx.x * 64;
    int tid = threadIdx.x;
    int ty = tid >> 4, tx = tid & 15;
    int lr = tid >> 2, lseg = tid & 3;
    float acc[4][4];
    #pragma unroll
    for (int i = 0; i < 4; i++)
        #pragma unroll
        for (int j = 0; j < 4; j++) acc[i][j] = 0.f;
    for (int d0 = 0; d0 < 256; d0 += 16) {
        __syncthreads();
        float4 va = *(const float4*)(A + (size_t)(m0 + lr) * 256 + d0 + lseg * 4);
        As[lseg * 4 + 0][lr] = va.x; As[lseg * 4 + 1][lr] = va.y;
        As[lseg * 4 + 2][lr] = va.z; As[lseg * 4 + 3][lr] = va.w;
        float4 vb = *(const float4*)(Bm + (size_t)(n0 + lr) * 256 + d0 + lseg * 4);
        Bs[lseg * 4 + 0][lr] = vb.x; Bs[lseg * 4 + 1][lr] = vb.y;
        Bs[lseg * 4 + 2][lr] = vb.z; Bs[lseg * 4 + 3][lr] = vb.w;
        __syncthreads();
        #pragma unroll
        for (int kk = 0; kk < 16; kk++) {
            float4 a = *(float4*)&As[kk][ty * 4];
            float4 b = *(float4*)&Bs[kk][tx * 4];
            float ar[4] = {a.x, a.y, a.z, a.w};
            float br[4] = {b.x, b.y, b.z, b.w};
            #pragma unroll
            for (int i = 0; i < 4; i++)
                #pragma unroll
                for (int j = 0; j < 4; j++) acc[i][j] += ar[i] * br[j];
        }
    }
    #pragma unroll
    for (int i = 0; i < 4; i++)
        #pragma unroll
        for (int j = 0; j < 4; j++) {
            float x = acc[i][j];
            if (mode == 0) x = 0.5f * x * (1.f + erff(x * 0.70710678118654752f));
            C[(size_t)(m0 + ty * 4 + i) * 256 + n0 + tx * 4 + j] = x;
        }
}

// -------- codebook: stats + bf16 hi/lo split --------
__global__ void __launch_bounds__(256) cb_split() {
    __shared__ float colp[256];
    int tid = threadIdx.x;
    colp[tid] = 0.f;
    __syncthreads();
    int w = tid >> 5, l = tid & 31;
    int row = blockIdx.x * 8 + w;
    const float4* p = (const float4*)(g_CB + (size_t)row * 256) + l * 2;
    float4 v0 = p[0], v1 = p[1];
    float xs[8] = {v0.x, v0.y, v0.z, v0.w, v1.x, v1.y, v1.z, v1.w};
    uint32_t hw[4], lw[4];
    #pragma unroll
    for (int t = 0; t < 4; t++) {
        __nv_bfloat16 h0 = __float2bfloat16_rn(xs[2 * t]);
        __nv_bfloat16 h1 = __float2bfloat16_rn(xs[2 * t + 1]);
        __nv_bfloat162 hp = __halves2bfloat162(h0, h1);
        hw[t] = *reinterpret_cast<uint32_t*>(&hp);
        __nv_bfloat16 l0 = __float2bfloat16_rn(xs[2 * t] - __bfloat162float(h0));
        __nv_bfloat16 l1 = __float2bfloat16_rn(xs[2 * t + 1] - __bfloat162float(h1));
        __nv_bfloat162 lp = __halves2bfloat162(l0, l1);
        lw[t] = *reinterpret_cast<uint32_t*>(&lp);
    }
    size_t base = (size_t)row * 256 + l * 8;
    *(uint4*)(g_CBhi + base) = make_uint4(hw[0], hw[1], hw[2], hw[3]);
    *(uint4*)(g_CBlo + base) = make_uint4(lw[0], lw[1], lw[2], lw[3]);
    float sq = 0.f;
    #pragma unroll
    for (int t = 0; t < 8; t++) sq += xs[t] * xs[t];
    float s = sq;
    #pragma unroll
    for (int o = 16; o; o >>= 1) s += __shfl_xor_sync(0xffffffffu, s, o);
    if (l == 0) { g_cbsq[row] = s; atomicAdd(&g_scal[1], s); }
    int dbase = l * 8;
    #pragma unroll
    for (int t = 0; t < 8; t++) atomicAdd(&colp[dbase + t], xs[t]);
    __syncthreads();
    atomicAdd(&g_csum[tid], colp[tid]);
}

// -------- z stats --------
__global__ void __launch_bounds__(256) z_stats(const float* __restrict__ z) {
    int blk = blockIdx.x;
    const float4* p = (const float4*)(z + (size_t)blk * THW);
    float s = 0.f, s2 = 0.f;
    #pragma unroll
    for (int j = 0; j < 8; j++) {
        float4 v = p[threadIdx.x + j * 256];
        s  += v.x + v.y + v.z + v.w;
        s2 += v.x * v.x + v.y * v.y + v.z * v.z + v.w * v.w;
    }
    float ts = blockReduceSum(s);
    float ts2 = blockReduceSum(s2);
    if (threadIdx.x == 0) {
        atomicAdd(&g_zcol[blk & 255], ts);
        atomicAdd(&g_scal[0], ts2);
    }
}

// -------- z transpose + bf16 hi/lo split: [B,D,THW] -> Zhi/Zlo[N][256] --------
__global__ void __launch_bounds__(256) zsplit(const float* __restrict__ z) {
    __shared__ float sm[32][261];
    int s0 = blockIdx.x * 256, d0 = blockIdx.y * 32, b = blockIdx.z;
    int t = threadIdx.x;
    const float* zp = z + ((size_t)b * 256 + d0) * THW + s0;
    #pragma unroll
    for (int i = 0; i < 32; i++) sm[i][t] = zp[(size_t)i * THW + t];
    __syncthreads();
    int dseg = t & 7, sl = t >> 3;
    #pragma unroll
    for (int w = 0; w < 8; w++) {
        int s_i = w * 32 + sl;
        float x0 = sm[dseg * 4 + 0][s_i];
        float x1 = sm[dseg * 4 + 1][s_i];
        float x2 = sm[dseg * 4 + 2][s_i];
        float x3 = sm[dseg * 4 + 3][s_i];
        __nv_bfloat16 h0 = __float2bfloat16_rn(x0), h1 = __float2bfloat16_rn(x1);
        __nv_bfloat16 h2 = __float2bfloat16_rn(x2), h3 = __float2bfloat16_rn(x3);
        __nv_bfloat162 hp0 = __halves2bfloat162(h0, h1);
        __nv_bfloat162 hp1 = __halves2bfloat162(h2, h3);
        __nv_bfloat16 l0 = __float2bfloat16_rn(x0 - __bfloat162float(h0));
        __nv_bfloat16 l1 = __float2bfloat16_rn(x1 - __bfloat162float(h1));
        __nv_bfloat16 l2 = __float2bfloat16_rn(x2 - __bfloat162float(h2));
        __nv_bfloat16 l3 = __float2bfloat16_rn(x3 - __bfloat162float(h3));
        __nv_bfloat162 lp0 = __halves2bfloat162(l0, l1);
        __nv_bfloat162 lp1 = __halves2bfloat162(l2, l3);
        size_t base = ((size_t)(b * THW + s0 + s_i) * 256) + d0 + dseg * 4;
        *(uint2*)(g_Zhi + base) = make_uint2(*reinterpret_cast<uint32_t*>(&hp0),
                                             *reinterpret_cast<uint32_t*>(&hp1));
        *(uint2*)(g_Zlo + base) = make_uint2(*reinterpret_cast<uint32_t*>(&lp0),
                                             *reinterpret_cast<uint32_t*>(&lp1));
    }
}

// ======== HMMA distance + fused argmin ========
// BM=128, BN=128, BK=32, 3-stage cp.async pipeline, 8 warps (warp tile 32x64).
// Smem stage: Ahi[0,8K) Alo[8K,16K) Bhi[16K,24K) Blo[24K,32K); rows 64B swizzled.
#define STAGE_BYTES 32768
#define SM_CBSQ     (3 * STAGE_BYTES)
#define SM_BEST     (SM_CBSQ + 512)
#define DIST_SMEM   (SM_BEST + 1024)

__device__ __forceinline__ void issue_chunk(uint32_t sb_stage, int m0, int n0,
                                            int kc, int tid) {
    int row = tid >> 2, c = tid & 3;
    int k0 = kc * 32;
    #pragma unroll
    for (int half = 0; half < 2; half++) {
        int r = row + half * 64;
        uint32_t so = (uint32_t)(r * 64 + ((c ^ ((r >> 1) & 3)) << 4));
        size_t gaA = (size_t)(m0 + r) * 256 + k0 + c * 8;
        size_t gaB = (size_t)(n0 + r) * 256 + k0 + c * 8;
        cpa16(sb_stage + so,         g_Zhi + gaA);
        cpa16(sb_stage + 8192 + so,  g_Zlo + gaA);
        cpa16(sb_stage + 16384 + so, g_CBhi + gaB);
        cpa16(sb_stage + 24576 + so, g_CBlo + gaB);
    }
    CP_COMMIT();
}

__global__ void __launch_bounds__(256) dist_hmma() {
    extern __shared__ __align__(1024) char smem[];
    uint32_t sb = smem_to_u32(smem);
    float* cbsq_s = (float*)(smem + SM_CBSQ);
    unsigned long long* bestsh = (unsigned long long*)(smem + SM_BEST);

    int tid = threadIdx.x, lane = tid & 31, wid = tid >> 5;
    int warp_m = wid >> 1, warp_n = wid & 1;
    int m0 = blockIdx.y * 128, n0 = blockIdx.x * 128;

    if (tid < 128) { cbsq_s[tid] = g_cbsq[n0 + tid]; bestsh[tid] = ~0ull; }

    // lane-constant fragment address pieces
    int la7 = lane & 7, l3 = (lane >> 3) & 1, l4 = lane >> 4;
    uint32_t aoff[2]; int aswz[2];
    #pragma unroll
    for (int mi = 0; mi < 2; mi++) {
        int r = warp_m * 32 + mi * 16 + la7 + l3 * 8;
        aoff[mi] = (uint32_t)(r * 64);
        aswz[mi] = (r >> 1) & 3;
    }
    uint32_t boff[4]; int bswz[4];
    #pragma unroll
    for (int g = 0; g < 4; g++) {
        int r = warp_n * 64 + g * 16 + la7 + l4 * 8;
        boff[g] = (uint32_t)(16384 + r * 64);
        bswz[g] = (r >> 1) & 3;
    }

    float acc[2][8][4];
    #pragma unroll
    for (int mi = 0; mi < 2; mi++)
        #pragma unroll
        for (int nj = 0; nj < 8; nj++)
            #pragma unroll
            for (int q = 0; q < 4; q++) acc[mi][nj][q] = 0.f;

    issue_chunk(sb, m0, n0, 0, tid);
    issue_chunk(sb + STAGE_BYTES, m0, n0, 1, tid);

    for (int kc = 0; kc < 8; kc++) {
        CP_WAIT1();
        __syncthreads();
        if (kc + 2 < 8)
            issue_chunk(sb + ((kc + 2) % 3) * STAGE_BYTES, m0, n0, kc + 2, tid);
        uint32_t st = sb + (kc % 3) * STAGE_BYTES;
        #pragma unroll
        for (int ki = 0; ki < 2; ki++) {
            uint32_t Ahi[2][4], Alo[2][4], Bhi[4][4], Blo[4][4];
            #pragma unroll
            for (int mi = 0; mi < 2; mi++) {
                uint32_t csel = (uint32_t)(((2 * ki + l4) ^ aswz[mi]) << 4);
                ldsm4(Ahi[mi], st + aoff[mi] + csel);
                ldsm4(Alo[mi], st + 8192 + aoff[mi] + csel);
            }
            #pragma unroll
            for (int g = 0; g < 4; g++) {
                uint32_t csel = (uint32_t)(((2 * ki + l3) ^ bswz[g]) << 4);
                ldsm4(Bhi[g], st + boff[g] + csel);
                ldsm4(Blo[g], st + 8192 + boff[g] + csel);
            }
            #pragma unroll
            for (int mi = 0; mi < 2; mi++)
                #pragma unroll
                for (int g = 0; g < 4; g++) {
                    mma16816(acc[mi][2 * g],     Ahi[mi], Bhi[g][0], Bhi[g][1]);
                    mma16816(acc[mi][2 * g + 1], Ahi[mi], Bhi[g][2], Bhi[g][3]);
                    mma16816(acc[mi][2 * g],     Alo[mi], Bhi[g][0], Bhi[g][1]);
                    mma16816(acc[mi][2 * g + 1], Alo[mi], Bhi[g][2], Bhi[g][3]);
                    mma16816(acc[mi][2 * g],     Ahi[mi], Blo[g][0], Blo[g][1]);
                    mma16816(acc[mi][2 * g + 1], Ahi[mi], Blo[g][2], Blo[g][3]);
                }
        }
    }

    // ---- fused argmin epilogue ----
    #pragma unroll
    for (int mi = 0; mi < 2; mi++)
        #pragma unroll
        for (int h = 0; h < 2; h++) {
            int rloc = warp_m * 32 + mi * 16 + (lane >> 2) + h * 8;
            unsigned long long best = ~0ull;
            #pragma unroll
            for (int nj = 0; nj < 8; nj++)
                #pragma unroll
                for (int e = 0; e < 2; e++) {
                    int col = warp_n * 64 + nj * 8 + (lane & 3) * 2 + e;
                    float sc = fmaf(-2.f, acc[mi][nj][h * 2 + e], cbsq_s[col]);
                    uint32_t fb = __float_as_uint(sc);
                    uint32_t key = (fb & 0x80000000u) ? ~fb : (fb | 0x80000000u);
                    unsigned long long u =
                        ((unsigned long long)key << 32) | (unsigned)(n0 + col);
                    best = best < u ? best : u;
                }
            atomicMin(&bestsh[rloc], best);
        }
    __syncthreads();
    if (tid < 128) atomicMin(&g_best[m0 + tid], bestsh[tid]);
}

// -------- gather z_q + loss + histogram --------
__global__ void __launch_bounds__(256) gather_loss(const float* __restrict__ z,
                                                   float* __restrict__ out) {
    unsigned int e = blockIdx.x * 256u + threadIdx.x;
    int b = e >> 21;
    int d = (e >> 13) & 255;
    int s = e & (THW - 1);
    int n = (b << 13) | s;
    int id = (int)(unsigned int)(g_best[n] & 0xffffffffull);
    float q = g_CB[(size_t)id * 256 + d];
    out[e] = q;
    if (d == 0) atomicAdd(&g_counts[id], 1);
    float diff = q - z[e];
    float ls = blockReduceSum(diff * diff);
    if (threadIdx.x == 0) atomicAdd(&g_scal[2], ls);
}

// -------- finalize scalars --------
__global__ void __launch_bounds__(256) finalize(float* __restrict__ out) {
    float ps = 0.f;
    for (int k = threadIdx.x; k < KK; k += 256) {
        float e = (float)g_counts[k] * (1.f / (float)NN);
        ps += e * logf(e + 1e-10f);
    }
    float ent = blockReduceSum(ps);
    float dp = (g_zcol[threadIdx.x] * (1.f / (float)NN)) *
               (g_csum[threadIdx.x] * (1.f / (float)KK));
    float dot = blockReduceSum(dp);
    if (threadIdx.x == 0) {
        float loss = 1.25f * g_scal[2] / (float)((size_t)NN * DD);
        float perp = expf(-ent);
        float meand = g_scal[0] / (float)NN + g_scal[1] / (float)KK - 2.f * dot;
        out[4194304] = loss;
        out[4194305] = perp;
        out[4194306] = meand;
    }
}

extern "C" void kernel_launch(void* const* d_in, const int* in_sizes, int n_in,
                              void* d_out, int out_size) {
    const float* z   = (const float*)d_in[0];
    const float* emb = (const float*)d_in[1];
    const float* w1  = (const float*)d_in[2];
    const float* w2  = (const float*)d_in[3];
    float* out = (float*)d_out;

    static int attr_done = 0;
    if (!attr_done) {
        cudaFuncSetAttribute(dist_hmma, cudaFuncAttributeMaxDynamicSharedMemorySize,
                             DIST_SMEM);
        attr_done = 1;
    }

    k_init<<<64, 256>>>();
    gemm_cb<<<dim3(4, 128), 256>>>(emb, w1, 0);
    gemm_cb<<<dim3(4, 128), 256>>>(emb, w2, 1);
    cb_split<<<1024, 256>>>();
    z_stats<<<512, 256>>>(z);
    zsplit<<<dim3(32, 8, 2), 256>>>(z);
    dist_hmma<<<dim3(64, 128), 256, DIST_SMEM>>>();
    gather_loss<<<16384, 256>>>(z, out);
    finalize<<<1, 256>>>(out);
}

// round 4
// speedup vs baseline: 3.4525x; 1.0164x over previous
#include <cuda_runtime.h>
#include <cuda_bf16.h>
#include <math.h>
#include <stdint.h>

// Problem constants (fixed by the dataset)
#define BB   2
#define DD   256
#define THW  8192
#define NN   16384
#define KK   8192

// -------- device scratch (no allocations allowed) --------
__device__ float g_H1[KK * DD];
__device__ float g_CB[KK * DD];
__device__ __nv_bfloat16 g_CBhi[KK * DD];
__device__ __nv_bfloat16 g_CBlo[KK * DD];
__device__ __nv_bfloat16 g_Zhi[NN * DD];
__device__ __nv_bfloat16 g_Zlo[NN * DD];
__device__ float g_cbsq[KK];
__device__ float g_csum[DD];
__device__ float g_zcol[DD];
__device__ float g_scal[3];
__device__ unsigned long long g_best[NN];
__device__ int   g_counts[KK];

// ================= PTX helpers (base sm_103-safe) =====
__device__ __forceinline__ uint32_t smem_to_u32(const void* p) {
    uint32_t a;
    asm("{ .reg .u64 t; cvta.to.shared.u64 t, %1; cvt.u32.u64 %0, t; }" : "=r"(a) : "l"(p));
    return a;
}
__device__ __forceinline__ void cpa16(uint32_t saddr, const void* g) {
    asm volatile("cp.async.cg.shared.global [%0], [%1], 16;" :: "r"(saddr), "l"(g) : "memory");
}
#define CP_COMMIT() asm volatile("cp.async.commit_group;" ::: "memory")
#define CP_WAIT1()  asm volatile("cp.async.wait_group 1;" ::: "memory")

__device__ __forceinline__ void ldsm4(uint32_t (&r)[4], uint32_t addr) {
    asm volatile("ldmatrix.sync.aligned.m8n8.x4.shared.b16 {%0,%1,%2,%3}, [%4];"
        : "=r"(r[0]), "=r"(r[1]), "=r"(r[2]), "=r"(r[3]) : "r"(addr));
}
__device__ __forceinline__ void mma16816(float (&d)[4], const uint32_t (&a)[4],
                                         uint32_t b0, uint32_t b1) {
    asm volatile("mma.sync.aligned.m16n8k16.row.col.f32.bf16.bf16.f32 "
        "{%0,%1,%2,%3}, {%4,%5,%6,%7}, {%8,%9}, {%0,%1,%2,%3};"
        : "+f"(d[0]), "+f"(d[1]), "+f"(d[2]), "+f"(d[3])
        : "r"(a[0]), "r"(a[1]), "r"(a[2]), "r"(a[3]), "r"(b0), "r"(b1));
}

// -------- helpers --------
__device__ __forceinline__ float blockReduceSum(float v) {
    __shared__ float sh[32];
    int lane = threadIdx.x & 31, w = threadIdx.x >> 5;
    #pragma unroll
    for (int o = 16; o; o >>= 1) v += __shfl_xor_sync(0xffffffffu, v, o);
    if (lane == 0) sh[w] = v;
    __syncthreads();
    v = (threadIdx.x < (blockDim.x >> 5)) ? sh[threadIdx.x] : 0.f;
    if (w == 0) {
        #pragma unroll
        for (int o = 16; o; o >>= 1) v += __shfl_xor_sync(0xffffffffu, v, o);
    }
    __syncthreads();
    return v;
}

__global__ void k_init() {
    int t = blockIdx.x * blockDim.x + threadIdx.x;
    if (t < NN) g_best[t] = ~0ull;
    if (t < KK) { g_counts[t] = 0; g_cbsq[t] = 0.f; }
    if (t < DD) { g_csum[t] = 0.f; g_zcol[t] = 0.f; }
    if (t < 3)  g_scal[t] = 0.f;
}

// -------- codebook GEMMs: C[M,256] = op(A @ B^T) --------
// mode 0: C=g_H1 with exact GELU.  mode 1: C=g_CB + fused split/stats epilogue.
__global__ void __launch_bounds__(256) gemm_cb(const float* __restrict__ Aext,
                                               const float* __restrict__ Bext,
                                               int mode) {
    const float* A = mode ? g_H1 : Aext;
    const float* Bm = Bext;
    __shared__ __align__(16) float As[16][64];
    __shared__ __align__(16) float Bs[16][64];
    __shared__ float colsum[64];
    int m0 = blockIdx.y * 64, n0 = blockIdx.x * 64;
    int tid = threadIdx.x;
    int ty = tid >> 4, tx = tid & 15;
    int lr = tid >> 2, lseg = tid & 3;
    if (mode && tid < 64) colsum[tid] = 0.f;
    float acc[4][4];
    #pragma unroll
    for (int i = 0; i < 4; i++)
        #pragma unroll
        for (int j = 0; j < 4; j++) acc[i][j] = 0.f;
    for (int d0 = 0; d0 < 256; d0 += 16) {
        __syncthreads();
        float4 va = *(const float4*)(A + (size_t)(m0 + lr) * 256 + d0 + lseg * 4);
        As[lseg * 4 + 0][lr] = va.x; As[lseg * 4 + 1][lr] = va.y;
        As[lseg * 4 + 2][lr] = va.z; As[lseg * 4 + 3][lr] = va.w;
        float4 vb = *(const float4*)(Bm + (size_t)(n0 + lr) * 256 + d0 + lseg * 4);
        Bs[lseg * 4 + 0][lr] = vb.x; Bs[lseg * 4 + 1][lr] = vb.y;
        Bs[lseg * 4 + 2][lr] = vb.z; Bs[lseg * 4 + 3][lr] = vb.w;
        __syncthreads();
        #pragma unroll
        for (int kk = 0; kk < 16; kk++) {
            float4 a = *(float4*)&As[kk][ty * 4];
            float4 b = *(float4*)&Bs[kk][tx * 4];
            float ar[4] = {a.x, a.y, a.z, a.w};
            float br[4] = {b.x, b.y, b.z, b.w};
            #pragma unroll
            for (int i = 0; i < 4; i++)
                #pragma unroll
                for (int j = 0; j < 4; j++) acc[i][j] += ar[i] * br[j];
        }
    }
    if (mode == 0) {
        #pragma unroll
        for (int i = 0; i < 4; i++)
            #pragma unroll
            for (int j = 0; j < 4; j++) {
                float x = acc[i][j];
                g_H1[(size_t)(m0 + ty * 4 + i) * 256 + n0 + tx * 4 + j] =
                    0.5f * x * (1.f + erff(x * 0.70710678118654752f));
            }
        return;
    }
    // ---- mode 1: write CB fp32, bf16 hi/lo split, row-sq, col-sums ----
    float sqtot = 0.f;
    float csumj[4] = {0.f, 0.f, 0.f, 0.f};
    #pragma unroll
    for (int i = 0; i < 4; i++) {
        size_t row = (size_t)(m0 + ty * 4 + i);
        float4 v = make_float4(acc[i][0], acc[i][1], acc[i][2], acc[i][3]);
        *(float4*)(g_CB + row * 256 + n0 + tx * 4) = v;
        uint32_t hw[2], lw[2];
        float xs[4] = {v.x, v.y, v.z, v.w};
        #pragma unroll
        for (int t = 0; t < 2; t++) {
            __nv_bfloat16 h0 = __float2bfloat16_rn(xs[2 * t]);
            __nv_bfloat16 h1 = __float2bfloat16_rn(xs[2 * t + 1]);
            __nv_bfloat162 hp = __halves2bfloat162(h0, h1);
            hw[t] = *reinterpret_cast<uint32_t*>(&hp);
            __nv_bfloat16 l0 = __float2bfloat16_rn(xs[2 * t] - __bfloat162float(h0));
            __nv_bfloat16 l1 = __float2bfloat16_rn(xs[2 * t + 1] - __bfloat162float(h1));
            __nv_bfloat162 lp = __halves2bfloat162(l0, l1);
            lw[t] = *reinterpret_cast<uint32_t*>(&lp);
        }
        *(uint2*)(g_CBhi + row * 256 + n0 + tx * 4) = make_uint2(hw[0], hw[1]);
        *(uint2*)(g_CBlo + row * 256 + n0 + tx * 4) = make_uint2(lw[0], lw[1]);
        float rsq = v.x * v.x + v.y * v.y + v.z * v.z + v.w * v.w;
        sqtot += rsq;
        // reduce rsq across the 16 tx lanes (contiguous within warp halves)
        #pragma unroll
        for (int o = 8; o; o >>= 1) rsq += __shfl_xor_sync(0xffffffffu, rsq, o, 16);
        if (tx == 0) atomicAdd(&g_cbsq[m0 + ty * 4 + i], rsq);
        csumj[0] += v.x; csumj[1] += v.y; csumj[2] += v.z; csumj[3] += v.w;
    }
    #pragma unroll
    for (int j = 0; j < 4; j++) atomicAdd(&colsum[tx * 4 + j], csumj[j]);
    float bs = blockReduceSum(sqtot);
    if (tid == 0) atomicAdd(&g_scal[1], bs);
    __syncthreads();
    if (tid < 64) atomicAdd(&g_csum[n0 + tid], colsum[tid]);
}

// -------- z transpose + bf16 split + stats: [B,D,THW] -> Zhi/Zlo[N][256] -----
__global__ void __launch_bounds__(256) zsplit(const float* __restrict__ z) {
    __shared__ float sm[32][261];
    __shared__ float zc[32];
    int s0 = blockIdx.x * 256, d0 = blockIdx.y * 32, b = blockIdx.z;
    int t = threadIdx.x;
    if (t < 32) zc[t] = 0.f;
    const float* zp = z + ((size_t)b * 256 + d0) * THW + s0;
    #pragma unroll
    for (int i = 0; i < 32; i++) sm[i][t] = zp[(size_t)i * THW + t];
    __syncthreads();
    // stats: thread (row i = t&31, chunk c = t>>5) sums 32 s-positions
    {
        int i = t & 31, c = t >> 5;
        float s = 0.f, s2 = 0.f;
        #pragma unroll
        for (int u = 0; u < 32; u++) {
            float v = sm[i][c * 32 + u];
            s += v; s2 += v * v;
        }
        atomicAdd(&zc[i], s);
        float ts2 = blockReduceSum(s2);
        if (t == 0) atomicAdd(&g_scal[0], ts2);
    }
    int dseg = t & 7, sl = t >> 3;
    #pragma unroll
    for (int w = 0; w < 8; w++) {
        int s_i = w * 32 + sl;
        float x0 = sm[dseg * 4 + 0][s_i];
        float x1 = sm[dseg * 4 + 1][s_i];
        float x2 = sm[dseg * 4 + 2][s_i];
        float x3 = sm[dseg * 4 + 3][s_i];
        __nv_bfloat16 h0 = __float2bfloat16_rn(x0), h1 = __float2bfloat16_rn(x1);
        __nv_bfloat16 h2 = __float2bfloat16_rn(x2), h3 = __float2bfloat16_rn(x3);
        __nv_bfloat162 hp0 = __halves2bfloat162(h0, h1);
        __nv_bfloat162 hp1 = __halves2bfloat162(h2, h3);
        __nv_bfloat16 l0 = __float2bfloat16_rn(x0 - __bfloat162float(h0));
        __nv_bfloat16 l1 = __float2bfloat16_rn(x1 - __bfloat162float(h1));
        __nv_bfloat16 l2 = __float2bfloat16_rn(x2 - __bfloat162float(h2));
        __nv_bfloat16 l3 = __float2bfloat16_rn(x3 - __bfloat162float(h3));
        __nv_bfloat162 lp0 = __halves2bfloat162(l0, l1);
        __nv_bfloat162 lp1 = __halves2bfloat162(l2, l3);
        size_t base = ((size_t)(b * THW + s0 + s_i) * 256) + d0 + dseg * 4;
        *(uint2*)(g_Zhi + base) = make_uint2(*reinterpret_cast<uint32_t*>(&hp0),
                                             *reinterpret_cast<uint32_t*>(&hp1));
        *(uint2*)(g_Zlo + base) = make_uint2(*reinterpret_cast<uint32_t*>(&lp0),
                                             *reinterpret_cast<uint32_t*>(&lp1));
    }
    __syncthreads();
    if (t < 32) atomicAdd(&g_zcol[d0 + t], zc[t]);
}

// ======== HMMA distance + fused argmin ========
// BM=128, BN=128, BK=32, 3-stage cp.async pipeline, 8 warps (warp tile 32x64).
#define STAGE_BYTES 32768
#define SM_CBSQ     (3 * STAGE_BYTES)
#define SM_BEST     (SM_CBSQ + 512)
#define DIST_SMEM   (SM_BEST + 1024)

__device__ __forceinline__ void issue_chunk(uint32_t sb_stage, int m0, int n0,
                                            int kc, int tid) {
    int row = tid >> 2, c = tid & 3;
    int k0 = kc * 32;
    #pragma unroll
    for (int half = 0; half < 2; half++) {
        int r = row + half * 64;
        uint32_t so = (uint32_t)(r * 64 + ((c ^ ((r >> 1) & 3)) << 4));
        size_t gaA = (size_t)(m0 + r) * 256 + k0 + c * 8;
        size_t gaB = (size_t)(n0 + r) * 256 + k0 + c * 8;
        cpa16(sb_stage + so,         g_Zhi + gaA);
        cpa16(sb_stage + 8192 + so,  g_Zlo + gaA);
        cpa16(sb_stage + 16384 + so, g_CBhi + gaB);
        cpa16(sb_stage + 24576 + so, g_CBlo + gaB);
    }
    CP_COMMIT();
}

__global__ void __launch_bounds__(256) dist_hmma() {
    extern __shared__ __align__(1024) char smem[];
    uint32_t sb = smem_to_u32(smem);
    float* cbsq_s = (float*)(smem + SM_CBSQ);
    unsigned long long* bestsh = (unsigned long long*)(smem + SM_BEST);

    int tid = threadIdx.x, lane = tid & 31, wid = tid >> 5;
    int warp_m = wid >> 1, warp_n = wid & 1;
    int m0 = blockIdx.y * 128, n0 = blockIdx.x * 128;

    if (tid < 128) { cbsq_s[tid] = g_cbsq[n0 + tid]; bestsh[tid] = ~0ull; }

    int la7 = lane & 7, l3 = (lane >> 3) & 1, l4 = lane >> 4;
    uint32_t aoff[2]; int aswz[2];
    #pragma unroll
    for (int mi = 0; mi < 2; mi++) {
        int r = warp_m * 32 + mi * 16 + la7 + l3 * 8;
        aoff[mi] = (uint32_t)(r * 64);
        aswz[mi] = (r >> 1) & 3;
    }
    uint32_t boff[4]; int bswz[4];
    #pragma unroll
    for (int g = 0; g < 4; g++) {
        int r = warp_n * 64 + g * 16 + la7 + l4 * 8;
        boff[g] = (uint32_t)(16384 + r * 64);
        bswz[g] = (r >> 1) & 3;
    }

    float acc[2][8][4];
    #pragma unroll
    for (int mi = 0; mi < 2; mi++)
        #pragma unroll
        for (int nj = 0; nj < 8; nj++)
            #pragma unroll
            for (int q = 0; q < 4; q++) acc[mi][nj][q] = 0.f;

    issue_chunk(sb, m0, n0, 0, tid);
    issue_chunk(sb + STAGE_BYTES, m0, n0, 1, tid);

    for (int kc = 0; kc < 8; kc++) {
        CP_WAIT1();
        __syncthreads();
        if (kc + 2 < 8)
            issue_chunk(sb + ((kc + 2) % 3) * STAGE_BYTES, m0, n0, kc + 2, tid);
        uint32_t st = sb + (kc % 3) * STAGE_BYTES;
        #pragma unroll
        for (int ki = 0; ki < 2; ki++) {
            uint32_t Ahi[2][4], Alo[2][4], Bhi[4][4], Blo[4][4];
            #pragma unroll
            for (int mi = 0; mi < 2; mi++) {
                uint32_t csel = (uint32_t)(((2 * ki + l4) ^ aswz[mi]) << 4);
                ldsm4(Ahi[mi], st + aoff[mi] + csel);
                ldsm4(Alo[mi], st + 8192 + aoff[mi] + csel);
            }
            #pragma unroll
            for (int g = 0; g < 4; g++) {
                uint32_t csel = (uint32_t)(((2 * ki + l3) ^ bswz[g]) << 4);
                ldsm4(Bhi[g], st + boff[g] + csel);
                ldsm4(Blo[g], st + 8192 + boff[g] + csel);
            }
            // term-major order: 16 independent MMAs per pass, no RAW stalls
            #pragma unroll
            for (int mi = 0; mi < 2; mi++)
                #pragma unroll
                for (int g = 0; g < 4; g++) {
                    mma16816(acc[mi][2 * g],     Ahi[mi], Bhi[g][0], Bhi[g][1]);
                    mma16816(acc[mi][2 * g + 1], Ahi[mi], Bhi[g][2], Bhi[g][3]);
                }
            #pragma unroll
            for (int mi = 0; mi < 2; mi++)
                #pragma unroll
                for (int g = 0; g < 4; g++) {
                    mma16816(acc[mi][2 * g],     Alo[mi], Bhi[g][0], Bhi[g][1]);
                    mma16816(acc[mi][2 * g + 1], Alo[mi], Bhi[g][2], Bhi[g][3]);
                }
            #pragma unroll
            for (int mi = 0; mi < 2; mi++)
                #pragma unroll
                for (int g = 0; g < 4; g++) {
                    mma16816(acc[mi][2 * g],     Ahi[mi], Blo[g][0], Blo[g][1]);
                    mma16816(acc[mi][2 * g + 1], Ahi[mi], Blo[g][2], Blo[g][3]);
                }
        }
    }

    // ---- fused argmin epilogue ----
    #pragma unroll
    for (int mi = 0; mi < 2; mi++)
        #pragma unroll
        for (int h = 0; h < 2; h++) {
            int rloc = warp_m * 32 + mi * 16 + (lane >> 2) + h * 8;
            unsigned long long best = ~0ull;
            #pragma unroll
            for (int nj = 0; nj < 8; nj++)
                #pragma unroll
                for (int e = 0; e < 2; e++) {
                    int col = warp_n * 64 + nj * 8 + (lane & 3) * 2 + e;
                    float sc = fmaf(-2.f, acc[mi][nj][h * 2 + e], cbsq_s[col]);
                    uint32_t fb = __float_as_uint(sc);
                    uint32_t key = (fb & 0x80000000u) ? ~fb : (fb | 0x80000000u);
                    unsigned long long u =
                        ((unsigned long long)key << 32) | (unsigned)(n0 + col);
                    best = best < u ? best : u;
                }
            atomicMin(&bestsh[rloc], best);
        }
    __syncthreads();
    if (tid < 128) atomicMin(&g_best[m0 + tid], bestsh[tid]);
}

// -------- gather z_q + loss + histogram --------
__global__ void __launch_bounds__(256) gather_loss(const float* __restrict__ z,
                                                   float* __restrict__ out) {
    unsigned int e = blockIdx.x * 256u + threadIdx.x;
    int b = e >> 21;
    int d = (e >> 13) & 255;
    int s = e & (THW - 1);
    int n = (b << 13) | s;
    int id = (int)(unsigned int)(g_best[n] & 0xffffffffull);
    float q = g_CB[(size_t)id * 256 + d];
    out[e] = q;
    if (d == 0) atomicAdd(&g_counts[id], 1);
    float diff = q - z[e];
    float ls = blockReduceSum(diff * diff);
    if (threadIdx.x == 0) atomicAdd(&g_scal[2], ls);
}

// -------- finalize scalars --------
__global__ void __launch_bounds__(256) finalize(float* __restrict__ out) {
    float ps = 0.f;
    for (int k = threadIdx.x; k < KK; k += 256) {
        float e = (float)g_counts[k] * (1.f / (float)NN);
        ps += e * logf(e + 1e-10f);
    }
    float ent = blockReduceSum(ps);
    float dp = (g_zcol[threadIdx.x] * (1.f / (float)NN)) *
               (g_csum[threadIdx.x] * (1.f / (float)KK));
    float dot = blockReduceSum(dp);
    if (threadIdx.x == 0) {
        float loss = 1.25f * g_scal[2] / (float)((size_t)NN * DD);
        float perp = expf(-ent);
        float meand = g_scal[0] / (float)NN + g_scal[1] / (float)KK - 2.f * dot;
        out[4194304] = loss;
        out[4194305] = perp;
        out[4194306] = meand;
    }
}

extern "C" void kernel_launch(void* const* d_in, const int* in_sizes, int n_in,
                              void* d_out, int out_size) {
    const float* z   = (const float*)d_in[0];
    const float* emb = (const float*)d_in[1];
    const float* w1  = (const float*)d_in[2];
    const float* w2  = (const float*)d_in[3];
    float* out = (float*)d_out;

    static int attr_done = 0;
    if (!attr_done) {
        cudaFuncSetAttribute(dist_hmma, cudaFuncAttributeMaxDynamicSharedMemorySize,
                             DIST_SMEM);
        attr_done = 1;
    }

    k_init<<<64, 256>>>();
    gemm_cb<<<dim3(4, 128), 256>>>(emb, w1, 0);
    gemm_cb<<<dim3(4, 128), 256>>>(emb, w2, 1);
    zsplit<<<dim3(32, 8, 2), 256>>>(z);
    dist_hmma<<<dim3(64, 128), 256, DIST_SMEM>>>();
    gather_loss<<<16384, 256>>>(z, out);
    finalize<<<1, 256>>>(out);
}

// round 5
// speedup vs baseline: 3.5871x; 1.0390x over previous
#include <cuda_runtime.h>
#include <cuda_bf16.h>
#include <math.h>
#include <stdint.h>

// Problem constants (fixed by the dataset)
#define BB   2
#define DD   256
#define THW  8192
#define NN   16384
#define KK   8192

// -------- device scratch (no allocations allowed) --------
__device__ float g_H1[KK * DD];
__device__ float g_CB[KK * DD];
__device__ __nv_bfloat16 g_CBhi[KK * DD];
__device__ __nv_bfloat16 g_CBlo[KK * DD];
__device__ __nv_bfloat16 g_Zhi[NN * DD];
__device__ __nv_bfloat16 g_Zlo[NN * DD];
__device__ float g_cbsq[KK];
__device__ float g_csum[DD];
__device__ float g_zcol[DD];
__device__ float g_scal[3];
__device__ unsigned long long g_best[NN];
__device__ int   g_counts[KK];

// ================= PTX helpers (base sm_103-safe) =====
__device__ __forceinline__ uint32_t smem_to_u32(const void* p) {
    uint32_t a;
    asm("{ .reg .u64 t; cvta.to.shared.u64 t, %1; cvt.u32.u64 %0, t; }" : "=r"(a) : "l"(p));
    return a;
}
__device__ __forceinline__ void cpa16(uint32_t saddr, const void* g) {
    asm volatile("cp.async.cg.shared.global [%0], [%1], 16;" :: "r"(saddr), "l"(g) : "memory");
}
#define CP_COMMIT() asm volatile("cp.async.commit_group;" ::: "memory")
#define CP_WAIT1()  asm volatile("cp.async.wait_group 1;" ::: "memory")

__device__ __forceinline__ void ldsm4(uint32_t (&r)[4], uint32_t addr) {
    asm volatile("ldmatrix.sync.aligned.m8n8.x4.shared.b16 {%0,%1,%2,%3}, [%4];"
        : "=r"(r[0]), "=r"(r[1]), "=r"(r[2]), "=r"(r[3]) : "r"(addr));
}
__device__ __forceinline__ void mma16816(float (&d)[4], const uint32_t (&a)[4],
                                         uint32_t b0, uint32_t b1) {
    asm volatile("mma.sync.aligned.m16n8k16.row.col.f32.bf16.bf16.f32 "
        "{%0,%1,%2,%3}, {%4,%5,%6,%7}, {%8,%9}, {%0,%1,%2,%3};"
        : "+f"(d[0]), "+f"(d[1]), "+f"(d[2]), "+f"(d[3])
        : "r"(a[0]), "r"(a[1]), "r"(a[2]), "r"(a[3]), "r"(b0), "r"(b1));
}

// -------- helpers --------
__device__ __forceinline__ float blockReduceSum(float v) {
    __shared__ float sh[32];
    int lane = threadIdx.x & 31, w = threadIdx.x >> 5;
    #pragma unroll
    for (int o = 16; o; o >>= 1) v += __shfl_xor_sync(0xffffffffu, v, o);
    if (lane == 0) sh[w] = v;
    __syncthreads();
    v = (threadIdx.x < (blockDim.x >> 5)) ? sh[threadIdx.x] : 0.f;
    if (w == 0) {
        #pragma unroll
        for (int o = 16; o; o >>= 1) v += __shfl_xor_sync(0xffffffffu, v, o);
    }
    __syncthreads();
    return v;
}

__global__ void k_init() {
    int t = blockIdx.x * blockDim.x + threadIdx.x;
    if (t < NN) g_best[t] = ~0ull;
    if (t < KK) { g_counts[t] = 0; g_cbsq[t] = 0.f; }
    if (t < DD) { g_csum[t] = 0.f; g_zcol[t] = 0.f; }
    if (t < 3)  g_scal[t] = 0.f;
}

// ======== fused: gemm0 (H1 = gelu(emb @ w1^T)) [z==0] + zsplit [z==1] ========
__global__ void __launch_bounds__(256) fused_pre(const float* __restrict__ z,
                                                 const float* __restrict__ emb,
                                                 const float* __restrict__ w1) {
    __shared__ __align__(16) float sh[8384];
    int tid = threadIdx.x;

    if (blockIdx.z == 0) {
        // ---------------- gemm0: H1 = gelu(emb @ w1^T) ----------------
        float (*As)[64] = (float (*)[64])sh;
        float (*Bs)[64] = (float (*)[64])(sh + 1024);
        int m0 = blockIdx.y * 64, n0 = blockIdx.x * 64;
        int ty = tid >> 4, tx = tid & 15;
        int lr = tid >> 2, lseg = tid & 3;
        float acc[4][4];
        #pragma unroll
        for (int i = 0; i < 4; i++)
            #pragma unroll
            for (int j = 0; j < 4; j++) acc[i][j] = 0.f;
        for (int d0 = 0; d0 < 256; d0 += 16) {
            __syncthreads();
            float4 va = *(const float4*)(emb + (size_t)(m0 + lr) * 256 + d0 + lseg * 4);
            As[lseg * 4 + 0][lr] = va.x; As[lseg * 4 + 1][lr] = va.y;
            As[lseg * 4 + 2][lr] = va.z; As[lseg * 4 + 3][lr] = va.w;
            float4 vb = *(const float4*)(w1 + (size_t)(n0 + lr) * 256 + d0 + lseg * 4);
            Bs[lseg * 4 + 0][lr] = vb.x; Bs[lseg * 4 + 1][lr] = vb.y;
            Bs[lseg * 4 + 2][lr] = vb.z; Bs[lseg * 4 + 3][lr] = vb.w;
            __syncthreads();
            #pragma unroll
            for (int kk = 0; kk < 16; kk++) {
                float4 a = *(float4*)&As[kk][ty * 4];
                float4 b = *(float4*)&Bs[kk][tx * 4];
                float ar[4] = {a.x, a.y, a.z, a.w};
                float br[4] = {b.x, b.y, b.z, b.w};
                #pragma unroll
                for (int i = 0; i < 4; i++)
                    #pragma unroll
                    for (int j = 0; j < 4; j++) acc[i][j] += ar[i] * br[j];
            }
        }
        #pragma unroll
        for (int i = 0; i < 4; i++)
            #pragma unroll
            for (int j = 0; j < 4; j++) {
                float x = acc[i][j];
                g_H1[(size_t)(m0 + ty * 4 + i) * 256 + n0 + tx * 4 + j] =
                    0.5f * x * (1.f + erff(x * 0.70710678118654752f));
            }
        return;
    }

    // ---------------- zsplit: transpose + bf16 split + stats ----------------
    float (*sm)[261] = (float (*)[261])sh;
    float* zc = sh + 8352;
    int idx = blockIdx.y * 4 + blockIdx.x;          // 0..511
    int s0 = (idx & 31) * 256, d0 = ((idx >> 5) & 7) * 32, b = idx >> 8;
    if (tid < 32) zc[tid] = 0.f;
    const float* zp = z + ((size_t)b * 256 + d0) * THW + s0;
    #pragma unroll
    for (int i = 0; i < 32; i++) sm[i][tid] = zp[(size_t)i * THW + tid];
    __syncthreads();
    {
        int i = tid & 31, c = tid >> 5;
        float s = 0.f, s2 = 0.f;
        #pragma unroll
        for (int u = 0; u < 32; u++) {
            float v = sm[i][c * 32 + u];
            s += v; s2 += v * v;
        }
        atomicAdd(&zc[i], s);
        float ts2 = blockReduceSum(s2);
        if (tid == 0) atomicAdd(&g_scal[0], ts2);
    }
    int dseg = tid & 7, sl = tid >> 3;
    #pragma unroll
    for (int w = 0; w < 8; w++) {
        int s_i = w * 32 + sl;
        float x0 = sm[dseg * 4 + 0][s_i];
        float x1 = sm[dseg * 4 + 1][s_i];
        float x2 = sm[dseg * 4 + 2][s_i];
        float x3 = sm[dseg * 4 + 3][s_i];
        __nv_bfloat16 h0 = __float2bfloat16_rn(x0), h1 = __float2bfloat16_rn(x1);
        __nv_bfloat16 h2 = __float2bfloat16_rn(x2), h3 = __float2bfloat16_rn(x3);
        __nv_bfloat162 hp0 = __halves2bfloat162(h0, h1);
        __nv_bfloat162 hp1 = __halves2bfloat162(h2, h3);
        __nv_bfloat16 l0 = __float2bfloat16_rn(x0 - __bfloat162float(h0));
        __nv_bfloat16 l1 = __float2bfloat16_rn(x1 - __bfloat162float(h1));
        __nv_bfloat16 l2 = __float2bfloat16_rn(x2 - __bfloat162float(h2));
        __nv_bfloat16 l3 = __float2bfloat16_rn(x3 - __bfloat162float(h3));
        __nv_bfloat162 lp0 = __halves2bfloat162(l0, l1);
        __nv_bfloat162 lp1 = __halves2bfloat162(l2, l3);
        size_t base = ((size_t)(b * THW + s0 + s_i) * 256) + d0 + dseg * 4;
        *(uint2*)(g_Zhi + base) = make_uint2(*reinterpret_cast<uint32_t*>(&hp0),
                                             *reinterpret_cast<uint32_t*>(&hp1));
        *(uint2*)(g_Zlo + base) = make_uint2(*reinterpret_cast<uint32_t*>(&lp0),
                                             *reinterpret_cast<uint32_t*>(&lp1));
    }
    __syncthreads();
    if (tid < 32) atomicAdd(&g_zcol[d0 + tid], zc[tid]);
}

// -------- gemm1: CB = H1 @ w2^T, fused split/stats epilogue --------
__global__ void __launch_bounds__(256) gemm_cb(const float* __restrict__ Bm) {
    __shared__ __align__(16) float As[16][64];
    __shared__ __align__(16) float Bs[16][64];
    __shared__ float colsum[64];
    int m0 = blockIdx.y * 64, n0 = blockIdx.x * 64;
    int tid = threadIdx.x;
    int ty = tid >> 4, tx = tid & 15;
    int lr = tid >> 2, lseg = tid & 3;
    if (tid < 64) colsum[tid] = 0.f;
    float acc[4][4];
    #pragma unroll
    for (int i = 0; i < 4; i++)
        #pragma unroll
        for (int j = 0; j < 4; j++) acc[i][j] = 0.f;
    for (int d0 = 0; d0 < 256; d0 += 16) {
        __syncthreads();
        float4 va = *(const float4*)(g_H1 + (size_t)(m0 + lr) * 256 + d0 + lseg * 4);
        As[lseg * 4 + 0][lr] = va.x; As[lseg * 4 + 1][lr] = va.y;
        As[lseg * 4 + 2][lr] = va.z; As[lseg * 4 + 3][lr] = va.w;
        float4 vb = *(const float4*)(Bm + (size_t)(n0 + lr) * 256 + d0 + lseg * 4);
        Bs[lseg * 4 + 0][lr] = vb.x; Bs[lseg * 4 + 1][lr] = vb.y;
        Bs[lseg * 4 + 2][lr] = vb.z; Bs[lseg * 4 + 3][lr] = vb.w;
        __syncthreads();
        #pragma unroll
        for (int kk = 0; kk < 16; kk++) {
            float4 a = *(float4*)&As[kk][ty * 4];
            float4 b = *(float4*)&Bs[kk][tx * 4];
            float ar[4] = {a.x, a.y, a.z, a.w};
            float br[4] = {b.x, b.y, b.z, b.w};
            #pragma unroll
            for (int i = 0; i < 4; i++)
                #pragma unroll
                for (int j = 0; j < 4; j++) acc[i][j] += ar[i] * br[j];
        }
    }
    float sqtot = 0.f;
    float csumj[4] = {0.f, 0.f, 0.f, 0.f};
    #pragma unroll
    for (int i = 0; i < 4; i++) {
        size_t row = (size_t)(m0 + ty * 4 + i);
        float4 v = make_float4(acc[i][0], acc[i][1], acc[i][2], acc[i][3]);
        *(float4*)(g_CB + row * 256 + n0 + tx * 4) = v;
        uint32_t hw[2], lw[2];
        float xs[4] = {v.x, v.y, v.z, v.w};
        #pragma unroll
        for (int t = 0; t < 2; t++) {
            __nv_bfloat16 h0 = __float2bfloat16_rn(xs[2 * t]);
            __nv_bfloat16 h1 = __float2bfloat16_rn(xs[2 * t + 1]);
            __nv_bfloat162 hp = __halves2bfloat162(h0, h1);
            hw[t] = *reinterpret_cast<uint32_t*>(&hp);
            __nv_bfloat16 l0 = __float2bfloat16_rn(xs[2 * t] - __bfloat162float(h0));
            __nv_bfloat16 l1 = __float2bfloat16_rn(xs[2 * t + 1] - __bfloat162float(h1));
            __nv_bfloat162 lp = __halves2bfloat162(l0, l1);
            lw[t] = *reinterpret_cast<uint32_t*>(&lp);
        }
        *(uint2*)(g_CBhi + row * 256 + n0 + tx * 4) = make_uint2(hw[0], hw[1]);
        *(uint2*)(g_CBlo + row * 256 + n0 + tx * 4) = make_uint2(lw[0], lw[1]);
        float rsq = v.x * v.x + v.y * v.y + v.z * v.z + v.w * v.w;
        sqtot += rsq;
        #pragma unroll
        for (int o = 8; o; o >>= 1) rsq += __shfl_xor_sync(0xffffffffu, rsq, o, 16);
        if (tx == 0) atomicAdd(&g_cbsq[m0 + ty * 4 + i], rsq);
        csumj[0] += v.x; csumj[1] += v.y; csumj[2] += v.z; csumj[3] += v.w;
    }
    #pragma unroll
    for (int j = 0; j < 4; j++) atomicAdd(&colsum[tx * 4 + j], csumj[j]);
    float bs = blockReduceSum(sqtot);
    if (tid == 0) atomicAdd(&g_scal[1], bs);
    __syncthreads();
    if (tid < 64) atomicAdd(&g_csum[n0 + tid], colsum[tid]);
}

// ======== HMMA distance + fused argmin ========
// BM=128, BN=128, BK=32, 3-stage cp.async pipeline, 8 warps (warp tile 32x64).
#define STAGE_BYTES 32768
#define SM_CBSQ     (3 * STAGE_BYTES)
#define SM_BEST     (SM_CBSQ + 512)
#define DIST_SMEM   (SM_BEST + 1024)

__device__ __forceinline__ void issue_chunk(uint32_t sb_stage, int m0, int n0,
                                            int kc, int tid) {
    int row = tid >> 2, c = tid & 3;
    int k0 = kc * 32;
    #pragma unroll
    for (int half = 0; half < 2; half++) {
        int r = row + half * 64;
        uint32_t so = (uint32_t)(r * 64 + ((c ^ ((r >> 1) & 3)) << 4));
        size_t gaA = (size_t)(m0 + r) * 256 + k0 + c * 8;
        size_t gaB = (size_t)(n0 + r) * 256 + k0 + c * 8;
        cpa16(sb_stage + so,         g_Zhi + gaA);
        cpa16(sb_stage + 8192 + so,  g_Zlo + gaA);
        cpa16(sb_stage + 16384 + so, g_CBhi + gaB);
        cpa16(sb_stage + 24576 + so, g_CBlo + gaB);
    }
    CP_COMMIT();
}

__global__ void __launch_bounds__(256, 2) dist_hmma() {
    extern __shared__ __align__(1024) char smem[];
    uint32_t sb = smem_to_u32(smem);
    float* cbsq_s = (float*)(smem + SM_CBSQ);
    unsigned long long* bestsh = (unsigned long long*)(smem + SM_BEST);

    int tid = threadIdx.x, lane = tid & 31, wid = tid >> 5;
    int warp_m = wid >> 1, warp_n = wid & 1;
    int m0 = blockIdx.y * 128, n0 = blockIdx.x * 128;

    if (tid < 128) { cbsq_s[tid] = g_cbsq[n0 + tid]; bestsh[tid] = ~0ull; }

    int la7 = lane & 7, l3 = (lane >> 3) & 1, l4 = lane >> 4;
    uint32_t aoff[2]; int aswz[2];
    #pragma unroll
    for (int mi = 0; mi < 2; mi++) {
        int r = warp_m * 32 + mi * 16 + la7 + l3 * 8;
        aoff[mi] = (uint32_t)(r * 64);
        aswz[mi] = (r >> 1) & 3;
    }
    uint32_t boff[4]; int bswz[4];
    #pragma unroll
    for (int g = 0; g < 4; g++) {
        int r = warp_n * 64 + g * 16 + la7 + l4 * 8;
        boff[g] = (uint32_t)(16384 + r * 64);
        bswz[g] = (r >> 1) & 3;
    }

    float acc[2][8][4];
    #pragma unroll
    for (int mi = 0; mi < 2; mi++)
        #pragma unroll
        for (int nj = 0; nj < 8; nj++)
            #pragma unroll
            for (int q = 0; q < 4; q++) acc[mi][nj][q] = 0.f;

    issue_chunk(sb, m0, n0, 0, tid);
    issue_chunk(sb + STAGE_BYTES, m0, n0, 1, tid);

    for (int kc = 0; kc < 8; kc++) {
        CP_WAIT1();
        __syncthreads();
        if (kc + 2 < 8)
            issue_chunk(sb + ((kc + 2) % 3) * STAGE_BYTES, m0, n0, kc + 2, tid);
        uint32_t st = sb + (kc % 3) * STAGE_BYTES;
        #pragma unroll
        for (int ki = 0; ki < 2; ki++) {
            uint32_t A0[2][4], A1[2][4], Bb[4][4];
            #pragma unroll
            for (int mi = 0; mi < 2; mi++) {
                uint32_t csel = (uint32_t)(((2 * ki + l4) ^ aswz[mi]) << 4);
                ldsm4(A0[mi], st + aoff[mi] + csel);
                ldsm4(A1[mi], st + 8192 + aoff[mi] + csel);
            }
            #pragma unroll
            for (int g = 0; g < 4; g++) {
                uint32_t csel = (uint32_t)(((2 * ki + l3) ^ bswz[g]) << 4);
                ldsm4(Bb[g], st + boff[g] + csel);
            }
            #pragma unroll
            for (int mi = 0; mi < 2; mi++)
                #pragma unroll
                for (int g = 0; g < 4; g++) {
                    mma16816(acc[mi][2 * g],     A0[mi], Bb[g][0], Bb[g][1]);
                    mma16816(acc[mi][2 * g + 1], A0[mi], Bb[g][2], Bb[g][3]);
                }
            #pragma unroll
            for (int mi = 0; mi < 2; mi++)
                #pragma unroll
                for (int g = 0; g < 4; g++) {
                    mma16816(acc[mi][2 * g],     A1[mi], Bb[g][0], Bb[g][1]);
                    mma16816(acc[mi][2 * g + 1], A1[mi], Bb[g][2], Bb[g][3]);
                }
            // reuse Bb for the lo B tiles
            #pragma unroll
            for (int g = 0; g < 4; g++) {
                uint32_t csel = (uint32_t)(((2 * ki + l3) ^ bswz[g]) << 4);
                ldsm4(Bb[g], st + 8192 + boff[g] + csel);
            }
            #pragma unroll
            for (int mi = 0; mi < 2; mi++)
                #pragma unroll
                for (int g = 0; g < 4; g++) {
                    mma16816(acc[mi][2 * g],     A0[mi], Bb[g][0], Bb[g][1]);
                    mma16816(acc[mi][2 * g + 1], A0[mi], Bb[g][2], Bb[g][3]);
                }
        }
    }

    // ---- fused argmin epilogue (quad shfl-reduce, then smem atomics) ----
    #pragma unroll
    for (int mi = 0; mi < 2; mi++)
        #pragma unroll
        for (int h = 0; h < 2; h++) {
            int rloc = warp_m * 32 + mi * 16 + (lane >> 2) + h * 8;
            unsigned long long best = ~0ull;
            #pragma unroll
            for (int nj = 0; nj < 8; nj++)
                #pragma unroll
                for (int e = 0; e < 2; e++) {
                    int col = warp_n * 64 + nj * 8 + (lane & 3) * 2 + e;
                    float sc = fmaf(-2.f, acc[mi][nj][h * 2 + e], cbsq_s[col]);
                    uint32_t fb = __float_as_uint(sc);
                    uint32_t key = (fb & 0x80000000u) ? ~fb : (fb | 0x80000000u);
                    unsigned long long u =
                        ((unsigned long long)key << 32) | (unsigned)(n0 + col);
                    best = best < u ? best : u;
                }
            unsigned long long o1 = __shfl_xor_sync(0xffffffffu, best, 1);
            best = best < o1 ? best : o1;
            unsigned long long o2 = __shfl_xor_sync(0xffffffffu, best, 2);
            best = best < o2 ? best : o2;
            if ((lane & 3) == 0) atomicMin(&bestsh[rloc], best);
        }
    __syncthreads();
    if (tid < 128) atomicMin(&g_best[m0 + tid], bestsh[tid]);
}

// -------- gather z_q + loss + histogram (coalesced CB rows) --------
__global__ void __launch_bounds__(256) gather_loss(const float* __restrict__ z,
                                                   float* __restrict__ out) {
    int x = blockIdx.x;                 // 0..255
    int b = x >> 7, s0 = (x & 127) * 64;
    int t = threadIdx.x;
    int s = s0 + (t & 63);
    int d4b = t >> 6;
    int n = b * THW + s;
    int id = (int)(unsigned int)(g_best[n] & 0xffffffffull);
    if (t < 64) atomicAdd(&g_counts[id], 1);
    const float* cbrow = g_CB + (size_t)id * 256;
    size_t ebase = ((size_t)b << 21) + s;
    float lsum = 0.f;
    #pragma unroll 4
    for (int it = 0; it < 16; it++) {
        int d4 = d4b + 4 * it;
        float4 q = *(const float4*)(cbrow + d4 * 4);
        size_t e = ebase + (size_t)(d4 * 4) * THW;
        float z0 = z[e];            out[e] = q.x;
        float z1 = z[e + THW];      out[e + THW] = q.y;
        float z2 = z[e + 2 * THW];  out[e + 2 * THW] = q.z;
        float z3 = z[e + 3 * THW];  out[e + 3 * THW] = q.w;
        float d0 = q.x - z0, d1 = q.y - z1, d2 = q.z - z2, d3 = q.w - z3;
        lsum += d0 * d0 + d1 * d1 + d2 * d2 + d3 * d3;
    }
    float ls = blockReduceSum(lsum);
    if (t == 0) atomicAdd(&g_scal[2], ls);
}

// -------- finalize scalars --------
__global__ void __launch_bounds__(256) finalize(float* __restrict__ out) {
    float ps = 0.f;
    for (int k = threadIdx.x; k < KK; k += 256) {
        float e = (float)g_counts[k] * (1.f / (float)NN);
        ps += e * logf(e + 1e-10f);
    }
    float ent = blockReduceSum(ps);
    float dp = (g_zcol[threadIdx.x] * (1.f / (float)NN)) *
               (g_csum[threadIdx.x] * (1.f / (float)KK));
    float dot = blockReduceSum(dp);
    if (threadIdx.x == 0) {
        float loss = 1.25f * g_scal[2] / (float)((size_t)NN * DD);
        float perp = expf(-ent);
        float meand = g_scal[0] / (float)NN + g_scal[1] / (float)KK - 2.f * dot;
        out[4194304] = loss;
        out[4194305] = perp;
        out[4194306] = meand;
    }
}

extern "C" void kernel_launch(void* const* d_in, const int* in_sizes, int n_in,
                              void* d_out, int out_size) {
    const float* z   = (const float*)d_in[0];
    const float* emb = (const float*)d_in[1];
    const float* w1  = (const float*)d_in[2];
    const float* w2  = (const float*)d_in[3];
    float* out = (float*)d_out;

    static int attr_done = 0;
    if (!attr_done) {
        cudaFuncSetAttribute(dist_hmma, cudaFuncAttributeMaxDynamicSharedMemorySize,
                             DIST_SMEM);
        attr_done = 1;
    }

    k_init<<<64, 256>>>();
    fused_pre<<<dim3(4, 128, 2), 256>>>(z, emb, w1);
    gemm_cb<<<dim3(4, 128), 256>>>(w2);
    dist_hmma<<<dim3(64, 128), 256, DIST_SMEM>>>();
    gather_loss<<<256, 256>>>(z, out);
    finalize<<<1, 256>>>(out);
}

// round 6
// speedup vs baseline: 4.9929x; 1.3919x over previous
#include <cuda_runtime.h>
#include <cuda_bf16.h>
#include <cuda_fp16.h>
#include <math.h>
#include <stdint.h>

// Problem constants (fixed by the dataset)
#define BB   2
#define DD   256
#define THW  8192
#define NN   16384
#define KK   8192

#define MARGIN 0.125f

// -------- device scratch (no allocations allowed) --------
__device__ float g_H1[KK * DD];
__device__ float g_CB[KK * DD];
__device__ __nv_bfloat16 g_CBhi[KK * DD];
__device__ __nv_bfloat16 g_CBlo[KK * DD];
__device__ __nv_bfloat16 g_Zhi[NN * DD];
__device__ __nv_bfloat16 g_Zlo[NN * DD];
__device__ __half2 g_S2[((size_t)NN * KK) / 2];   // approx scores, 256 MB
__device__ float g_cbsq[KK];
__device__ float g_csum[DD];
__device__ float g_zcol[DD];
__device__ float g_scal[3];
__device__ unsigned long long g_best[NN];
__device__ int   g_counts[KK];

// ================= PTX helpers (base sm_103-safe) =====
__device__ __forceinline__ uint32_t smem_to_u32(const void* p) {
    uint32_t a;
    asm("{ .reg .u64 t; cvta.to.shared.u64 t, %1; cvt.u32.u64 %0, t; }" : "=r"(a) : "l"(p));
    return a;
}
__device__ __forceinline__ void cpa16(uint32_t saddr, const void* g) {
    asm volatile("cp.async.cg.shared.global [%0], [%1], 16;" :: "r"(saddr), "l"(g) : "memory");
}
#define CP_COMMIT() asm volatile("cp.async.commit_group;" ::: "memory")
#define CP_WAIT1()  asm volatile("cp.async.wait_group 1;" ::: "memory")

__device__ __forceinline__ void ldsm4(uint32_t (&r)[4], uint32_t addr) {
    asm volatile("ldmatrix.sync.aligned.m8n8.x4.shared.b16 {%0,%1,%2,%3}, [%4];"
        : "=r"(r[0]), "=r"(r[1]), "=r"(r[2]), "=r"(r[3]) : "r"(addr));
}
__device__ __forceinline__ void mma16816(float (&d)[4], const uint32_t (&a)[4],
                                         uint32_t b0, uint32_t b1) {
    asm volatile("mma.sync.aligned.m16n8k16.row.col.f32.bf16.bf16.f32 "
        "{%0,%1,%2,%3}, {%4,%5,%6,%7}, {%8,%9}, {%0,%1,%2,%3};"
        : "+f"(d[0]), "+f"(d[1]), "+f"(d[2]), "+f"(d[3])
        : "r"(a[0]), "r"(a[1]), "r"(a[2]), "r"(a[3]), "r"(b0), "r"(b1));
}

// -------- helpers --------
__device__ __forceinline__ float blockReduceSum(float v) {
    __shared__ float sh[32];
    int lane = threadIdx.x & 31, w = threadIdx.x >> 5;
    #pragma unroll
    for (int o = 16; o; o >>= 1) v += __shfl_xor_sync(0xffffffffu, v, o);
    if (lane == 0) sh[w] = v;
    __syncthreads();
    v = (threadIdx.x < (blockDim.x >> 5)) ? sh[threadIdx.x] : 0.f;
    if (w == 0) {
        #pragma unroll
        for (int o = 16; o; o >>= 1) v += __shfl_xor_sync(0xffffffffu, v, o);
    }
    __syncthreads();
    return v;
}

__global__ void k_init() {
    int t = blockIdx.x * blockDim.x + threadIdx.x;
    if (t < NN) g_best[t] = ~0ull;
    if (t < KK) { g_counts[t] = 0; g_cbsq[t] = 0.f; }
    if (t < DD) { g_csum[t] = 0.f; g_zcol[t] = 0.f; }
    if (t < 3)  g_scal[t] = 0.f;
}

// ======== fused: gemm0 (H1 = gelu(emb @ w1^T)) [z==0] + zsplit [z==1] ========
__global__ void __launch_bounds__(256) fused_pre(const float* __restrict__ z,
                                                 const float* __restrict__ emb,
                                                 const float* __restrict__ w1) {
    __shared__ __align__(16) float sh[8384];
    int tid = threadIdx.x;

    if (blockIdx.z == 0) {
        float (*As)[64] = (float (*)[64])sh;
        float (*Bs)[64] = (float (*)[64])(sh + 1024);
        int m0 = blockIdx.y * 64, n0 = blockIdx.x * 64;
        int ty = tid >> 4, tx = tid & 15;
        int lr = tid >> 2, lseg = tid & 3;
        float acc[4][4];
        #pragma unroll
        for (int i = 0; i < 4; i++)
            #pragma unroll
            for (int j = 0; j < 4; j++) acc[i][j] = 0.f;
        for (int d0 = 0; d0 < 256; d0 += 16) {
            __syncthreads();
            float4 va = *(const float4*)(emb + (size_t)(m0 + lr) * 256 + d0 + lseg * 4);
            As[lseg * 4 + 0][lr] = va.x; As[lseg * 4 + 1][lr] = va.y;
            As[lseg * 4 + 2][lr] = va.z; As[lseg * 4 + 3][lr] = va.w;
            float4 vb = *(const float4*)(w1 + (size_t)(n0 + lr) * 256 + d0 + lseg * 4);
            Bs[lseg * 4 + 0][lr] = vb.x; Bs[lseg * 4 + 1][lr] = vb.y;
            Bs[lseg * 4 + 2][lr] = vb.z; Bs[lseg * 4 + 3][lr] = vb.w;
            __syncthreads();
            #pragma unroll
            for (int kk = 0; kk < 16; kk++) {
                float4 a = *(float4*)&As[kk][ty * 4];
                float4 b = *(float4*)&Bs[kk][tx * 4];
                float ar[4] = {a.x, a.y, a.z, a.w};
                float br[4] = {b.x, b.y, b.z, b.w};
                #pragma unroll
                for (int i = 0; i < 4; i++)
                    #pragma unroll
                    for (int j = 0; j < 4; j++) acc[i][j] += ar[i] * br[j];
            }
        }
        #pragma unroll
        for (int i = 0; i < 4; i++)
            #pragma unroll
            for (int j = 0; j < 4; j++) {
                float x = acc[i][j];
                g_H1[(size_t)(m0 + ty * 4 + i) * 256 + n0 + tx * 4 + j] =
                    0.5f * x * (1.f + erff(x * 0.70710678118654752f));
            }
        return;
    }

    // ---------------- zsplit: transpose + bf16 split + stats ----------------
    float (*sm)[261] = (float (*)[261])sh;
    float* zc = sh + 8352;
    int idx = blockIdx.y * 4 + blockIdx.x;
    int s0 = (idx & 31) * 256, d0 = ((idx >> 5) & 7) * 32, b = idx >> 8;
    if (tid < 32) zc[tid] = 0.f;
    const float* zp = z + ((size_t)b * 256 + d0) * THW + s0;
    #pragma unroll
    for (int i = 0; i < 32; i++) sm[i][tid] = zp[(size_t)i * THW + tid];
    __syncthreads();
    {
        int i = tid & 31, c = tid >> 5;
        float s = 0.f, s2 = 0.f;
        #pragma unroll
        for (int u = 0; u < 32; u++) {
            float v = sm[i][c * 32 + u];
            s += v; s2 += v * v;
        }
        atomicAdd(&zc[i], s);
        float ts2 = blockReduceSum(s2);
        if (tid == 0) atomicAdd(&g_scal[0], ts2);
    }
    int dseg = tid & 7, sl = tid >> 3;
    #pragma unroll
    for (int w = 0; w < 8; w++) {
        int s_i = w * 32 + sl;
        float x0 = sm[dseg * 4 + 0][s_i];
        float x1 = sm[dseg * 4 + 1][s_i];
        float x2 = sm[dseg * 4 + 2][s_i];
        float x3 = sm[dseg * 4 + 3][s_i];
        __nv_bfloat16 h0 = __float2bfloat16_rn(x0), h1 = __float2bfloat16_rn(x1);
        __nv_bfloat16 h2 = __float2bfloat16_rn(x2), h3 = __float2bfloat16_rn(x3);
        __nv_bfloat162 hp0 = __halves2bfloat162(h0, h1);
        __nv_bfloat162 hp1 = __halves2bfloat162(h2, h3);
        __nv_bfloat16 l0 = __float2bfloat16_rn(x0 - __bfloat162float(h0));
        __nv_bfloat16 l1 = __float2bfloat16_rn(x1 - __bfloat162float(h1));
        __nv_bfloat16 l2 = __float2bfloat16_rn(x2 - __bfloat162float(h2));
        __nv_bfloat16 l3 = __float2bfloat16_rn(x3 - __bfloat162float(h3));
        __nv_bfloat162 lp0 = __halves2bfloat162(l0, l1);
        __nv_bfloat162 lp1 = __halves2bfloat162(l2, l3);
        size_t base = ((size_t)(b * THW + s0 + s_i) * 256) + d0 + dseg * 4;
        *(uint2*)(g_Zhi + base) = make_uint2(*reinterpret_cast<uint32_t*>(&hp0),
                                             *reinterpret_cast<uint32_t*>(&hp1));
        *(uint2*)(g_Zlo + base) = make_uint2(*reinterpret_cast<uint32_t*>(&lp0),
                                             *reinterpret_cast<uint32_t*>(&lp1));
    }
    __syncthreads();
    if (tid < 32) atomicAdd(&g_zcol[d0 + tid], zc[tid]);
}

// -------- gemm1: CB = H1 @ w2^T, fused split/stats epilogue --------
__global__ void __launch_bounds__(256) gemm_cb(const float* __restrict__ Bm) {
    __shared__ __align__(16) float As[16][64];
    __shared__ __align__(16) float Bs[16][64];
    __shared__ float colsum[64];
    int m0 = blockIdx.y * 64, n0 = blockIdx.x * 64;
    int tid = threadIdx.x;
    int ty = tid >> 4, tx = tid & 15;
    int lr = tid >> 2, lseg = tid & 3;
    if (tid < 64) colsum[tid] = 0.f;
    float acc[4][4];
    #pragma unroll
    for (int i = 0; i < 4; i++)
        #pragma unroll
        for (int j = 0; j < 4; j++) acc[i][j] = 0.f;
    for (int d0 = 0; d0 < 256; d0 += 16) {
        __syncthreads();
        float4 va = *(const float4*)(g_H1 + (size_t)(m0 + lr) * 256 + d0 + lseg * 4);
        As[lseg * 4 + 0][lr] = va.x; As[lseg * 4 + 1][lr] = va.y;
        As[lseg * 4 + 2][lr] = va.z; As[lseg * 4 + 3][lr] = va.w;
        float4 vb = *(const float4*)(Bm + (size_t)(n0 + lr) * 256 + d0 + lseg * 4);
        Bs[lseg * 4 + 0][lr] = vb.x; Bs[lseg * 4 + 1][lr] = vb.y;
        Bs[lseg * 4 + 2][lr] = vb.z; Bs[lseg * 4 + 3][lr] = vb.w;
        __syncthreads();
        #pragma unroll
        for (int kk = 0; kk < 16; kk++) {
            float4 a = *(float4*)&As[kk][ty * 4];
            float4 b = *(float4*)&Bs[kk][tx * 4];
            float ar[4] = {a.x, a.y, a.z, a.w};
            float br[4] = {b.x, b.y, b.z, b.w};
            #pragma unroll
            for (int i = 0; i < 4; i++)
                #pragma unroll
                for (int j = 0; j < 4; j++) acc[i][j] += ar[i] * br[j];
        }
    }
    float sqtot = 0.f;
    float csumj[4] = {0.f, 0.f, 0.f, 0.f};
    #pragma unroll
    for (int i = 0; i < 4; i++) {
        size_t row = (size_t)(m0 + ty * 4 + i);
        float4 v = make_float4(acc[i][0], acc[i][1], acc[i][2], acc[i][3]);
        *(float4*)(g_CB + row * 256 + n0 + tx * 4) = v;
        uint32_t hw[2], lw[2];
        float xs[4] = {v.x, v.y, v.z, v.w};
        #pragma unroll
        for (int t = 0; t < 2; t++) {
            __nv_bfloat16 h0 = __float2bfloat16_rn(xs[2 * t]);
            __nv_bfloat16 h1 = __float2bfloat16_rn(xs[2 * t + 1]);
            __nv_bfloat162 hp = __halves2bfloat162(h0, h1);
            hw[t] = *reinterpret_cast<uint32_t*>(&hp);
            __nv_bfloat16 l0 = __float2bfloat16_rn(xs[2 * t] - __bfloat162float(h0));
            __nv_bfloat16 l1 = __float2bfloat16_rn(xs[2 * t + 1] - __bfloat162float(h1));
            __nv_bfloat162 lp = __halves2bfloat162(l0, l1);
            lw[t] = *reinterpret_cast<uint32_t*>(&lp);
        }
        *(uint2*)(g_CBhi + row * 256 + n0 + tx * 4) = make_uint2(hw[0], hw[1]);
        *(uint2*)(g_CBlo + row * 256 + n0 + tx * 4) = make_uint2(lw[0], lw[1]);
        float rsq = v.x * v.x + v.y * v.y + v.z * v.z + v.w * v.w;
        sqtot += rsq;
        #pragma unroll
        for (int o = 8; o; o >>= 1) rsq += __shfl_xor_sync(0xffffffffu, rsq, o, 16);
        if (tx == 0) atomicAdd(&g_cbsq[m0 + ty * 4 + i], rsq);
        csumj[0] += v.x; csumj[1] += v.y; csumj[2] += v.z; csumj[3] += v.w;
    }
    #pragma unroll
    for (int j = 0; j < 4; j++) atomicAdd(&colsum[tx * 4 + j], csumj[j]);
    float bs = blockReduceSum(sqtot);
    if (tid == 0) atomicAdd(&g_scal[1], bs);
    __syncthreads();
    if (tid < 64) atomicAdd(&g_csum[n0 + tid], colsum[tid]);
}

// ======== approx HMMA distance (hi*hi only) + score dump + approx argmin ====
#define STAGE_BYTES 16384
#define SM_CBSQ     (3 * STAGE_BYTES)
#define SM_BEST     (SM_CBSQ + 512)
#define DIST_SMEM   (SM_BEST + 1024)

__device__ __forceinline__ void issue_chunk(uint32_t sb_stage, int m0, int n0,
                                            int kc, int tid) {
    int row = tid >> 2, c = tid & 3;
    int k0 = kc * 32;
    #pragma unroll
    for (int half = 0; half < 2; half++) {
        int r = row + half * 64;
        uint32_t so = (uint32_t)(r * 64 + ((c ^ ((r >> 1) & 3)) << 4));
        cpa16(sb_stage + so,        g_Zhi + (size_t)(m0 + r) * 256 + k0 + c * 8);
        cpa16(sb_stage + 8192 + so, g_CBhi + (size_t)(n0 + r) * 256 + k0 + c * 8);
    }
    CP_COMMIT();
}

__global__ void __launch_bounds__(256, 2) dist_approx() {
    extern __shared__ __align__(1024) char smem[];
    uint32_t sb = smem_to_u32(smem);
    float* cbsq_s = (float*)(smem + SM_CBSQ);
    unsigned long long* bestsh = (unsigned long long*)(smem + SM_BEST);

    int tid = threadIdx.x, lane = tid & 31, wid = tid >> 5;
    int warp_m = wid >> 1, warp_n = wid & 1;
    int m0 = blockIdx.y * 128, n0 = blockIdx.x * 128;

    if (tid < 128) { cbsq_s[tid] = g_cbsq[n0 + tid]; bestsh[tid] = ~0ull; }

    int la7 = lane & 7, l3 = (lane >> 3) & 1, l4 = lane >> 4;
    uint32_t aoff[2]; int aswz[2];
    #pragma unroll
    for (int mi = 0; mi < 2; mi++) {
        int r = warp_m * 32 + mi * 16 + la7 + l3 * 8;
        aoff[mi] = (uint32_t)(r * 64);
        aswz[mi] = (r >> 1) & 3;
    }
    uint32_t boff[4]; int bswz[4];
    #pragma unroll
    for (int g = 0; g < 4; g++) {
        int r = warp_n * 64 + g * 16 + la7 + l4 * 8;
        boff[g] = (uint32_t)(8192 + r * 64);
        bswz[g] = (r >> 1) & 3;
    }

    float acc[2][8][4];
    #pragma unroll
    for (int mi = 0; mi < 2; mi++)
        #pragma unroll
        for (int nj = 0; nj < 8; nj++)
            #pragma unroll
            for (int q = 0; q < 4; q++) acc[mi][nj][q] = 0.f;

    issue_chunk(sb, m0, n0, 0, tid);
    issue_chunk(sb + STAGE_BYTES, m0, n0, 1, tid);

    for (int kc = 0; kc < 8; kc++) {
        CP_WAIT1();
        __syncthreads();
        if (kc + 2 < 8)
            issue_chunk(sb + ((kc + 2) % 3) * STAGE_BYTES, m0, n0, kc + 2, tid);
        uint32_t st = sb + (kc % 3) * STAGE_BYTES;
        #pragma unroll
        for (int ki = 0; ki < 2; ki++) {
            uint32_t A0[2][4], Bb[4][4];
            #pragma unroll
            for (int mi = 0; mi < 2; mi++) {
                uint32_t csel = (uint32_t)(((2 * ki + l4) ^ aswz[mi]) << 4);
                ldsm4(A0[mi], st + aoff[mi] + csel);
            }
            #pragma unroll
            for (int g = 0; g < 4; g++) {
                uint32_t csel = (uint32_t)(((2 * ki + l3) ^ bswz[g]) << 4);
                ldsm4(Bb[g], st + boff[g] + csel);
            }
            #pragma unroll
            for (int mi = 0; mi < 2; mi++)
                #pragma unroll
                for (int g = 0; g < 4; g++) {
                    mma16816(acc[mi][2 * g],     A0[mi], Bb[g][0], Bb[g][1]);
                    mma16816(acc[mi][2 * g + 1], A0[mi], Bb[g][2], Bb[g][3]);
                }
        }
    }

    // ---- epilogue: fp16 score dump + approx argmin ----
    #pragma unroll
    for (int mi = 0; mi < 2; mi++)
        #pragma unroll
        for (int h = 0; h < 2; h++) {
            int rloc = warp_m * 32 + mi * 16 + (lane >> 2) + h * 8;
            size_t rowb = (size_t)(m0 + rloc) * KK + n0 + warp_n * 64 + (lane & 3) * 2;
            unsigned long long best = ~0ull;
            #pragma unroll
            for (int nj = 0; nj < 8; nj++) {
                int colb = warp_n * 64 + nj * 8 + (lane & 3) * 2;
                float sc0 = fmaf(-2.f, acc[mi][nj][h * 2],     cbsq_s[colb]);
                float sc1 = fmaf(-2.f, acc[mi][nj][h * 2 + 1], cbsq_s[colb + 1]);
                g_S2[(rowb + nj * 8) >> 1] = __floats2half2_rn(sc0, sc1);
                #pragma unroll
                for (int e = 0; e < 2; e++) {
                    float sc = e ? sc1 : sc0;
                    uint32_t fb = __float_as_uint(sc);
                    uint32_t key = (fb & 0x80000000u) ? ~fb : (fb | 0x80000000u);
                    unsigned long long u =
                        ((unsigned long long)key << 32) | (unsigned)(n0 + colb + e);
                    best = best < u ? best : u;
                }
            }
            unsigned long long o1 = __shfl_xor_sync(0xffffffffu, best, 1);
            best = best < o1 ? best : o1;
            unsigned long long o2 = __shfl_xor_sync(0xffffffffu, best, 2);
            best = best < o2 ? best : o2;
            if ((lane & 3) == 0) atomicMin(&bestsh[rloc], best);
        }
    __syncthreads();
    if (tid < 128) atomicMin(&g_best[m0 + tid], bestsh[tid]);
}

// ======== refine: exact fp32 re-score of near-best candidates ========
__global__ void __launch_bounds__(256) refine() {
    int wid = threadIdx.x >> 5, lane = threadIdx.x & 31;
    int n = blockIdx.x * 8 + wid;

    // reconstruct this token's z row (dims lane*8 .. lane*8+7)
    uint4 vh = *(const uint4*)(g_Zhi + (size_t)n * 256 + lane * 8);
    uint4 vl = *(const uint4*)(g_Zlo + (size_t)n * 256 + lane * 8);
    float zf[8];
    {
        const __nv_bfloat162* hp = (const __nv_bfloat162*)&vh;
        const __nv_bfloat162* lp = (const __nv_bfloat162*)&vl;
        #pragma unroll
        for (int t = 0; t < 4; t++) {
            float2 fh = __bfloat1622float2(hp[t]);
            float2 fl = __bfloat1622float2(lp[t]);
            zf[2 * t] = fh.x + fl.x;
            zf[2 * t + 1] = fh.y + fl.y;
        }
    }

    unsigned long long ab = g_best[n];
    uint32_t akey = (uint32_t)(ab >> 32);
    uint32_t afb = (akey & 0x80000000u) ? (akey & 0x7fffffffu) : ~akey;
    float thresh = __uint_as_float(afb) + MARGIN;

    unsigned long long best = ~0ull;
    const uint4* Srow = (const uint4*)(((const __half*)g_S2) + (size_t)n * KK);
    for (int it = 0; it < 32; it++) {
        uint4 v = Srow[it * 32 + lane];
        float s[8];
        {
            const __half2* hp = (const __half2*)&v;
            #pragma unroll
            for (int t = 0; t < 4; t++) {
                float2 f = __half22float2(hp[t]);
                s[2 * t] = f.x; s[2 * t + 1] = f.y;
            }
        }
        bool any8 = false;
        #pragma unroll
        for (int j = 0; j < 8; j++) any8 |= (s[j] <= thresh);
        if (__ballot_sync(0xffffffffu, any8) == 0) continue;
        #pragma unroll
        for (int j = 0; j < 8; j++) {
            unsigned m = __ballot_sync(0xffffffffu, s[j] <= thresh);
            while (m) {
                int src = __ffs(m) - 1;
                m &= m - 1;
                int code = (it * 32 + src) * 8 + j;
                const float4* cb = (const float4*)(g_CB + (size_t)code * 256 + lane * 8);
                float4 c0 = cb[0], c1 = cb[1];
                float d = zf[0] * c0.x + zf[1] * c0.y + zf[2] * c0.z + zf[3] * c0.w
                        + zf[4] * c1.x + zf[5] * c1.y + zf[6] * c1.z + zf[7] * c1.w;
                #pragma unroll
                for (int o = 16; o; o >>= 1) d += __shfl_xor_sync(0xffffffffu, d, o);
                float sc = fmaf(-2.f, d, g_cbsq[code]);
                uint32_t fb = __float_as_uint(sc);
                uint32_t key = (fb & 0x80000000u) ? ~fb : (fb | 0x80000000u);
                unsigned long long u = ((unsigned long long)key << 32) | (unsigned)code;
                best = best < u ? best : u;
            }
        }
    }
    if (lane == 0) g_best[n] = best;
}

// -------- gather z_q + loss + histogram (coalesced CB rows) --------
__global__ void __launch_bounds__(256) gather_loss(const float* __restrict__ z,
                                                   float* __restrict__ out) {
    int x = blockIdx.x;
    int b = x >> 7, s0 = (x & 127) * 64;
    int t = threadIdx.x;
    int s = s0 + (t & 63);
    int d4b = t >> 6;
    int n = b * THW + s;
    int id = (int)(unsigned int)(g_best[n] & 0xffffffffull);
    if (t < 64) atomicAdd(&g_counts[id], 1);
    const float* cbrow = g_CB + (size_t)id * 256;
    size_t ebase = ((size_t)b << 21) + s;
    float lsum = 0.f;
    #pragma unroll 4
    for (int it = 0; it < 16; it++) {
        int d4 = d4b + 4 * it;
        float4 q = *(const float4*)(cbrow + d4 * 4);
        size_t e = ebase + (size_t)(d4 * 4) * THW;
        float z0 = z[e];            out[e] = q.x;
        float z1 = z[e + THW];      out[e + THW] = q.y;
        float z2 = z[e + 2 * THW];  out[e + 2 * THW] = q.z;
        float z3 = z[e + 3 * THW];  out[e + 3 * THW] = q.w;
        float d0 = q.x - z0, d1 = q.y - z1, d2 = q.z - z2, d3 = q.w - z3;
        lsum += d0 * d0 + d1 * d1 + d2 * d2 + d3 * d3;
    }
    float ls = blockReduceSum(lsum);
    if (t == 0) atomicAdd(&g_scal[2], ls);
}

// -------- finalize scalars --------
__global__ void __launch_bounds__(256) finalize(float* __restrict__ out) {
    float ps = 0.f;
    for (int k = threadIdx.x; k < KK; k += 256) {
        float e = (float)g_counts[k] * (1.f / (float)NN);
        ps += e * logf(e + 1e-10f);
    }
    float ent = blockReduceSum(ps);
    float dp = (g_zcol[threadIdx.x] * (1.f / (float)NN)) *
               (g_csum[threadIdx.x] * (1.f / (float)KK));
    float dot = blockReduceSum(dp);
    if (threadIdx.x == 0) {
        float loss = 1.25f * g_scal[2] / (float)((size_t)NN * DD);
        float perp = expf(-ent);
        float meand = g_scal[0] / (float)NN + g_scal[1] / (float)KK - 2.f * dot;
        out[4194304] = loss;
        out[4194305] = perp;
        out[4194306] = meand;
    }
}

extern "C" void kernel_launch(void* const* d_in, const int* in_sizes, int n_in,
                              void* d_out, int out_size) {
    const float* z   = (const float*)d_in[0];
    const float* emb = (const float*)d_in[1];
    const float* w1  = (const float*)d_in[2];
    const float* w2  = (const float*)d_in[3];
    float* out = (float*)d_out;

    static int attr_done = 0;
    if (!attr_done) {
        cudaFuncSetAttribute(dist_approx, cudaFuncAttributeMaxDynamicSharedMemorySize,
                             DIST_SMEM);
        attr_done = 1;
    }

    k_init<<<64, 256>>>();
    fused_pre<<<dim3(4, 128, 2), 256>>>(z, emb, w1);
    gemm_cb<<<dim3(4, 128), 256>>>(w2);
    dist_approx<<<dim3(64, 128), 256, DIST_SMEM>>>();
    refine<<<2048, 256>>>();
    gather_loss<<<256, 256>>>(z, out);
    finalize<<<1, 256>>>(out);
}

// round 7
// speedup vs baseline: 5.5668x; 1.1149x over previous
#include <cuda_runtime.h>
#include <cuda_bf16.h>
#include <math.h>
#include <stdint.h>

// Problem constants (fixed by the dataset)
#define BB   2
#define DD   256
#define THW  8192
#define NN   16384
#define KK   8192

#define MARGIN 0.125f
#define CAP    1024

// -------- device scratch (no allocations allowed) --------
__device__ float g_H1[KK * DD];
__device__ float g_CB[KK * DD];
__device__ __nv_bfloat16 g_CBhi[KK * DD];
__device__ __nv_bfloat16 g_CBlo[KK * DD];
__device__ __nv_bfloat16 g_Zhi[NN * DD];
__device__ __nv_bfloat16 g_Zlo[NN * DD];
__device__ float g_cbsq[KK];
__device__ float g_csum[DD];
__device__ float g_zcol[DD];
__device__ float g_scal[3];
__device__ unsigned long long g_best[NN];
__device__ int   g_counts[KK];
__device__ int   g_ccount[NN];
__device__ unsigned short g_cand[(size_t)NN * CAP];   // 32 MB

// ================= PTX helpers (base sm_103-safe) =====
__device__ __forceinline__ uint32_t smem_to_u32(const void* p) {
    uint32_t a;
    asm("{ .reg .u64 t; cvta.to.shared.u64 t, %1; cvt.u32.u64 %0, t; }" : "=r"(a) : "l"(p));
    return a;
}
__device__ __forceinline__ void cpa16(uint32_t saddr, const void* g) {
    asm volatile("cp.async.cg.shared.global [%0], [%1], 16;" :: "r"(saddr), "l"(g) : "memory");
}
#define CP_COMMIT() asm volatile("cp.async.commit_group;" ::: "memory")
#define CP_WAIT1()  asm volatile("cp.async.wait_group 1;" ::: "memory")

__device__ __forceinline__ void ldsm4(uint32_t (&r)[4], uint32_t addr) {
    asm volatile("ldmatrix.sync.aligned.m8n8.x4.shared.b16 {%0,%1,%2,%3}, [%4];"
        : "=r"(r[0]), "=r"(r[1]), "=r"(r[2]), "=r"(r[3]) : "r"(addr));
}
__device__ __forceinline__ void mma16816(float (&d)[4], const uint32_t (&a)[4],
                                         uint32_t b0, uint32_t b1) {
    asm volatile("mma.sync.aligned.m16n8k16.row.col.f32.bf16.bf16.f32 "
        "{%0,%1,%2,%3}, {%4,%5,%6,%7}, {%8,%9}, {%0,%1,%2,%3};"
        : "+f"(d[0]), "+f"(d[1]), "+f"(d[2]), "+f"(d[3])
        : "r"(a[0]), "r"(a[1]), "r"(a[2]), "r"(a[3]), "r"(b0), "r"(b1));
}

// -------- helpers --------
__device__ __forceinline__ float blockReduceSum(float v) {
    __shared__ float sh[32];
    int lane = threadIdx.x & 31, w = threadIdx.x >> 5;
    #pragma unroll
    for (int o = 16; o; o >>= 1) v += __shfl_xor_sync(0xffffffffu, v, o);
    if (lane == 0) sh[w] = v;
    __syncthreads();
    v = (threadIdx.x < (blockDim.x >> 5)) ? sh[threadIdx.x] : 0.f;
    if (w == 0) {
        #pragma unroll
        for (int o = 16; o; o >>= 1) v += __shfl_xor_sync(0xffffffffu, v, o);
    }
    __syncthreads();
    return v;
}

__global__ void k_init() {
    int t = blockIdx.x * blockDim.x + threadIdx.x;
    if (t < NN) { g_best[t] = ~0ull; g_ccount[t] = 0; }
    if (t < KK) { g_counts[t] = 0; g_cbsq[t] = 0.f; }
    if (t < DD) { g_csum[t] = 0.f; g_zcol[t] = 0.f; }
    if (t < 3)  g_scal[t] = 0.f;
}

// ======== fused: gemm0 (H1 = gelu(emb @ w1^T)) [z==0] + zsplit [z==1] ========
__global__ void __launch_bounds__(256) fused_pre(const float* __restrict__ z,
                                                 const float* __restrict__ emb,
                                                 const float* __restrict__ w1) {
    __shared__ __align__(16) float sh[8384];
    int tid = threadIdx.x;

    if (blockIdx.z == 0) {
        float (*As)[64] = (float (*)[64])sh;
        float (*Bs)[64] = (float (*)[64])(sh + 1024);
        int m0 = blockIdx.y * 64, n0 = blockIdx.x * 64;
        int ty = tid >> 4, tx = tid & 15;
        int lr = tid >> 2, lseg = tid & 3;
        float acc[4][4];
        #pragma unroll
        for (int i = 0; i < 4; i++)
            #pragma unroll
            for (int j = 0; j < 4; j++) acc[i][j] = 0.f;
        for (int d0 = 0; d0 < 256; d0 += 16) {
            __syncthreads();
            float4 va = *(const float4*)(emb + (size_t)(m0 + lr) * 256 + d0 + lseg * 4);
            As[lseg * 4 + 0][lr] = va.x; As[lseg * 4 + 1][lr] = va.y;
            As[lseg * 4 + 2][lr] = va.z; As[lseg * 4 + 3][lr] = va.w;
            float4 vb = *(const float4*)(w1 + (size_t)(n0 + lr) * 256 + d0 + lseg * 4);
            Bs[lseg * 4 + 0][lr] = vb.x; Bs[lseg * 4 + 1][lr] = vb.y;
            Bs[lseg * 4 + 2][lr] = vb.z; Bs[lseg * 4 + 3][lr] = vb.w;
            __syncthreads();
            #pragma unroll
            for (int kk = 0; kk < 16; kk++) {
                float4 a = *(float4*)&As[kk][ty * 4];
                float4 b = *(float4*)&Bs[kk][tx * 4];
                float ar[4] = {a.x, a.y, a.z, a.w};
                float br[4] = {b.x, b.y, b.z, b.w};
                #pragma unroll
                for (int i = 0; i < 4; i++)
                    #pragma unroll
                    for (int j = 0; j < 4; j++) acc[i][j] += ar[i] * br[j];
            }
        }
        #pragma unroll
        for (int i = 0; i < 4; i++)
            #pragma unroll
            for (int j = 0; j < 4; j++) {
                float x = acc[i][j];
                g_H1[(size_t)(m0 + ty * 4 + i) * 256 + n0 + tx * 4 + j] =
                    0.5f * x * (1.f + erff(x * 0.70710678118654752f));
            }
        return;
    }

    // ---------------- zsplit: transpose + bf16 split + stats ----------------
    float (*sm)[261] = (float (*)[261])sh;
    float* zc = sh + 8352;
    int idx = blockIdx.y * 4 + blockIdx.x;
    int s0 = (idx & 31) * 256, d0 = ((idx >> 5) & 7) * 32, b = idx >> 8;
    if (tid < 32) zc[tid] = 0.f;
    const float* zp = z + ((size_t)b * 256 + d0) * THW + s0;
    #pragma unroll
    for (int i = 0; i < 32; i++) sm[i][tid] = zp[(size_t)i * THW + tid];
    __syncthreads();
    {
        int i = tid & 31, c = tid >> 5;
        float s = 0.f, s2 = 0.f;
        #pragma unroll
        for (int u = 0; u < 32; u++) {
            float v = sm[i][c * 32 + u];
            s += v; s2 += v * v;
        }
        atomicAdd(&zc[i], s);
        float ts2 = blockReduceSum(s2);
        if (tid == 0) atomicAdd(&g_scal[0], ts2);
    }
    int dseg = tid & 7, sl = tid >> 3;
    #pragma unroll
    for (int w = 0; w < 8; w++) {
        int s_i = w * 32 + sl;
        float x0 = sm[dseg * 4 + 0][s_i];
        float x1 = sm[dseg * 4 + 1][s_i];
        float x2 = sm[dseg * 4 + 2][s_i];
        float x3 = sm[dseg * 4 + 3][s_i];
        __nv_bfloat16 h0 = __float2bfloat16_rn(x0), h1 = __float2bfloat16_rn(x1);
        __nv_bfloat16 h2 = __float2bfloat16_rn(x2), h3 = __float2bfloat16_rn(x3);
        __nv_bfloat162 hp0 = __halves2bfloat162(h0, h1);
        __nv_bfloat162 hp1 = __halves2bfloat162(h2, h3);
        __nv_bfloat16 l0 = __float2bfloat16_rn(x0 - __bfloat162float(h0));
        __nv_bfloat16 l1 = __float2bfloat16_rn(x1 - __bfloat162float(h1));
        __nv_bfloat16 l2 = __float2bfloat16_rn(x2 - __bfloat162float(h2));
        __nv_bfloat16 l3 = __float2bfloat16_rn(x3 - __bfloat162float(h3));
        __nv_bfloat162 lp0 = __halves2bfloat162(l0, l1);
        __nv_bfloat162 lp1 = __halves2bfloat162(l2, l3);
        size_t base = ((size_t)(b * THW + s0 + s_i) * 256) + d0 + dseg * 4;
        *(uint2*)(g_Zhi + base) = make_uint2(*reinterpret_cast<uint32_t*>(&hp0),
                                             *reinterpret_cast<uint32_t*>(&hp1));
        *(uint2*)(g_Zlo + base) = make_uint2(*reinterpret_cast<uint32_t*>(&lp0),
                                             *reinterpret_cast<uint32_t*>(&lp1));
    }
    __syncthreads();
    if (tid < 32) atomicAdd(&g_zcol[d0 + tid], zc[tid]);
}

// -------- gemm1: CB = H1 @ w2^T, fused split/stats epilogue --------
__global__ void __launch_bounds__(256) gemm_cb(const float* __restrict__ Bm) {
    __shared__ __align__(16) float As[16][64];
    __shared__ __align__(16) float Bs[16][64];
    __shared__ float colsum[64];
    int m0 = blockIdx.y * 64, n0 = blockIdx.x * 64;
    int tid = threadIdx.x;
    int ty = tid >> 4, tx = tid & 15;
    int lr = tid >> 2, lseg = tid & 3;
    if (tid < 64) colsum[tid] = 0.f;
    float acc[4][4];
    #pragma unroll
    for (int i = 0; i < 4; i++)
        #pragma unroll
        for (int j = 0; j < 4; j++) acc[i][j] = 0.f;
    for (int d0 = 0; d0 < 256; d0 += 16) {
        __syncthreads();
        float4 va = *(const float4*)(g_H1 + (size_t)(m0 + lr) * 256 + d0 + lseg * 4);
        As[lseg * 4 + 0][lr] = va.x; As[lseg * 4 + 1][lr] = va.y;
        As[lseg * 4 + 2][lr] = va.z; As[lseg * 4 + 3][lr] = va.w;
        float4 vb = *(const float4*)(Bm + (size_t)(n0 + lr) * 256 + d0 + lseg * 4);
        Bs[lseg * 4 + 0][lr] = vb.x; Bs[lseg * 4 + 1][lr] = vb.y;
        Bs[lseg * 4 + 2][lr] = vb.z; Bs[lseg * 4 + 3][lr] = vb.w;
        __syncthreads();
        #pragma unroll
        for (int kk = 0; kk < 16; kk++) {
            float4 a = *(float4*)&As[kk][ty * 4];
            float4 b = *(float4*)&Bs[kk][tx * 4];
            float ar[4] = {a.x, a.y, a.z, a.w};
            float br[4] = {b.x, b.y, b.z, b.w};
            #pragma unroll
            for (int i = 0; i < 4; i++)
                #pragma unroll
                for (int j = 0; j < 4; j++) acc[i][j] += ar[i] * br[j];
        }
    }
    float sqtot = 0.f;
    float csumj[4] = {0.f, 0.f, 0.f, 0.f};
    #pragma unroll
    for (int i = 0; i < 4; i++) {
        size_t row = (size_t)(m0 + ty * 4 + i);
        float4 v = make_float4(acc[i][0], acc[i][1], acc[i][2], acc[i][3]);
        *(float4*)(g_CB + row * 256 + n0 + tx * 4) = v;
        uint32_t hw[2], lw[2];
        float xs[4] = {v.x, v.y, v.z, v.w};
        #pragma unroll
        for (int t = 0; t < 2; t++) {
            __nv_bfloat16 h0 = __float2bfloat16_rn(xs[2 * t]);
            __nv_bfloat16 h1 = __float2bfloat16_rn(xs[2 * t + 1]);
            __nv_bfloat162 hp = __halves2bfloat162(h0, h1);
            hw[t] = *reinterpret_cast<uint32_t*>(&hp);
            __nv_bfloat16 l0 = __float2bfloat16_rn(xs[2 * t] - __bfloat162float(h0));
            __nv_bfloat16 l1 = __float2bfloat16_rn(xs[2 * t + 1] - __bfloat162float(h1));
            __nv_bfloat162 lp = __halves2bfloat162(l0, l1);
            lw[t] = *reinterpret_cast<uint32_t*>(&lp);
        }
        *(uint2*)(g_CBhi + row * 256 + n0 + tx * 4) = make_uint2(hw[0], hw[1]);
        *(uint2*)(g_CBlo + row * 256 + n0 + tx * 4) = make_uint2(lw[0], lw[1]);
        float rsq = v.x * v.x + v.y * v.y + v.z * v.z + v.w * v.w;
        sqtot += rsq;
        #pragma unroll
        for (int o = 8; o; o >>= 1) rsq += __shfl_xor_sync(0xffffffffu, rsq, o, 16);
        if (tx == 0) atomicAdd(&g_cbsq[m0 + ty * 4 + i], rsq);
        csumj[0] += v.x; csumj[1] += v.y; csumj[2] += v.z; csumj[3] += v.w;
    }
    #pragma unroll
    for (int j = 0; j < 4; j++) atomicAdd(&colsum[tx * 4 + j], csumj[j]);
    float bs = blockReduceSum(sqtot);
    if (tid == 0) atomicAdd(&g_scal[1], bs);
    __syncthreads();
    if (tid < 64) atomicAdd(&g_csum[n0 + tid], colsum[tid]);
}

// ======== approx HMMA distance (hi*hi only) + candidate push ====
#define STAGE_BYTES 16384
#define SM_CBSQ     (3 * STAGE_BYTES)
#define SM_BEST     (SM_CBSQ + 512)
#define SM_THRESH   (SM_BEST + 1024)
#define DIST_SMEM   (SM_THRESH + 512)

__device__ __forceinline__ void issue_chunk(uint32_t sb_stage, int m0, int n0,
                                            int kc, int tid) {
    int row = tid >> 2, c = tid & 3;
    int k0 = kc * 32;
    #pragma unroll
    for (int half = 0; half < 2; half++) {
        int r = row + half * 64;
        uint32_t so = (uint32_t)(r * 64 + ((c ^ ((r >> 1) & 3)) << 4));
        cpa16(sb_stage + so,        g_Zhi + (size_t)(m0 + r) * 256 + k0 + c * 8);
        cpa16(sb_stage + 8192 + so, g_CBhi + (size_t)(n0 + r) * 256 + k0 + c * 8);
    }
    CP_COMMIT();
}

__global__ void __launch_bounds__(256, 2) dist_approx() {
    extern __shared__ __align__(1024) char smem[];
    uint32_t sb = smem_to_u32(smem);
    float* cbsq_s = (float*)(smem + SM_CBSQ);
    unsigned long long* bestsh = (unsigned long long*)(smem + SM_BEST);
    float* threshsh = (float*)(smem + SM_THRESH);

    int tid = threadIdx.x, lane = tid & 31, wid = tid >> 5;
    int warp_m = wid >> 1, warp_n = wid & 1;
    int m0 = blockIdx.y * 128, n0 = blockIdx.x * 128;

    if (tid < 128) { cbsq_s[tid] = g_cbsq[n0 + tid]; bestsh[tid] = ~0ull; }

    int la7 = lane & 7, l3 = (lane >> 3) & 1, l4 = lane >> 4;
    uint32_t aoff[2]; int aswz[2];
    #pragma unroll
    for (int mi = 0; mi < 2; mi++) {
        int r = warp_m * 32 + mi * 16 + la7 + l3 * 8;
        aoff[mi] = (uint32_t)(r * 64);
        aswz[mi] = (r >> 1) & 3;
    }
    uint32_t boff[4]; int bswz[4];
    #pragma unroll
    for (int g = 0; g < 4; g++) {
        int r = warp_n * 64 + g * 16 + la7 + l4 * 8;
        boff[g] = (uint32_t)(8192 + r * 64);
        bswz[g] = (r >> 1) & 3;
    }

    float acc[2][8][4];
    #pragma unroll
    for (int mi = 0; mi < 2; mi++)
        #pragma unroll
        for (int nj = 0; nj < 8; nj++)
            #pragma unroll
            for (int q = 0; q < 4; q++) acc[mi][nj][q] = 0.f;

    issue_chunk(sb, m0, n0, 0, tid);
    issue_chunk(sb + STAGE_BYTES, m0, n0, 1, tid);

    for (int kc = 0; kc < 8; kc++) {
        CP_WAIT1();
        __syncthreads();
        if (kc + 2 < 8)
            issue_chunk(sb + ((kc + 2) % 3) * STAGE_BYTES, m0, n0, kc + 2, tid);
        uint32_t st = sb + (kc % 3) * STAGE_BYTES;
        #pragma unroll
        for (int ki = 0; ki < 2; ki++) {
            uint32_t A0[2][4], Bb[4][4];
            #pragma unroll
            for (int mi = 0; mi < 2; mi++) {
                uint32_t csel = (uint32_t)(((2 * ki + l4) ^ aswz[mi]) << 4);
                ldsm4(A0[mi], st + aoff[mi] + csel);
            }
            #pragma unroll
            for (int g = 0; g < 4; g++) {
                uint32_t csel = (uint32_t)(((2 * ki + l3) ^ bswz[g]) << 4);
                ldsm4(Bb[g], st + boff[g] + csel);
            }
            #pragma unroll
            for (int mi = 0; mi < 2; mi++)
                #pragma unroll
                for (int g = 0; g < 4; g++) {
                    mma16816(acc[mi][2 * g],     A0[mi], Bb[g][0], Bb[g][1]);
                    mma16816(acc[mi][2 * g + 1], A0[mi], Bb[g][2], Bb[g][3]);
                }
        }
    }

    // ---- pass 1: local argmin (float compares), quad reduce, atomicMin ----
    #pragma unroll
    for (int mi = 0; mi < 2; mi++)
        #pragma unroll
        for (int h = 0; h < 2; h++) {
            int rloc = warp_m * 32 + mi * 16 + (lane >> 2) + h * 8;
            float bestv = 3.4e38f;
            int besti = 0;
            #pragma unroll
            for (int nj = 0; nj < 8; nj++)
                #pragma unroll
                for (int e = 0; e < 2; e++) {
                    int col = warp_n * 64 + nj * 8 + (lane & 3) * 2 + e;
                    float sc = fmaf(-2.f, acc[mi][nj][h * 2 + e], cbsq_s[col]);
                    if (sc < bestv) { bestv = sc; besti = n0 + col; }
                }
            uint32_t fb = __float_as_uint(bestv);
            uint32_t key = (fb & 0x80000000u) ? ~fb : (fb | 0x80000000u);
            unsigned long long best =
                ((unsigned long long)key << 32) | (unsigned)besti;
            unsigned long long o1 = __shfl_xor_sync(0xffffffffu, best, 1);
            best = best < o1 ? best : o1;
            unsigned long long o2 = __shfl_xor_sync(0xffffffffu, best, 2);
            best = best < o2 ? best : o2;
            if ((lane & 3) == 0) atomicMin(&bestsh[rloc], best);
        }
    __syncthreads();
    if (tid < 128) {
        unsigned long long mine = bestsh[tid];
        unsigned long long old = atomicMin(&g_best[m0 + tid], mine);
        unsigned long long merged = old < mine ? old : mine;
        uint32_t key = (uint32_t)(merged >> 32);
        uint32_t fb = (key & 0x80000000u) ? (key & 0x7fffffffu) : ~key;
        threshsh[tid] = __uint_as_float(fb) + MARGIN;
    }
    __syncthreads();

    // ---- pass 2: push candidates within margin of best-so-far ----
    #pragma unroll
    for (int mi = 0; mi < 2; mi++)
        #pragma unroll
        for (int h = 0; h < 2; h++) {
            int rloc = warp_m * 32 + mi * 16 + (lane >> 2) + h * 8;
            float th = threshsh[rloc];
            int token = m0 + rloc;
            #pragma unroll
            for (int nj = 0; nj < 8; nj++)
                #pragma unroll
                for (int e = 0; e < 2; e++) {
                    int col = warp_n * 64 + nj * 8 + (lane & 3) * 2 + e;
                    float sc = fmaf(-2.f, acc[mi][nj][h * 2 + e], cbsq_s[col]);
                    if (sc <= th) {
                        int ix = atomicAdd(&g_ccount[token], 1);
                        if (ix < CAP)
                            g_cand[(size_t)token * CAP + ix] =
                                (unsigned short)(n0 + col);
                    }
                }
        }
}

// ======== refine: exact fp32 re-score of pushed candidates ========
__global__ void __launch_bounds__(256) refine() {
    int wid = threadIdx.x >> 5, lane = threadIdx.x & 31;
    int n = blockIdx.x * 8 + wid;
    int cnt = g_ccount[n];
    if (cnt > CAP) cnt = CAP;

    // reconstruct this token's z row (dims lane*8 .. lane*8+7)
    uint4 vh = *(const uint4*)(g_Zhi + (size_t)n * 256 + lane * 8);
    uint4 vl = *(const uint4*)(g_Zlo + (size_t)n * 256 + lane * 8);
    float zf[8];
    {
        const __nv_bfloat162* hp = (const __nv_bfloat162*)&vh;
        const __nv_bfloat162* lp = (const __nv_bfloat162*)&vl;
        #pragma unroll
        for (int t = 0; t < 4; t++) {
            float2 fh = __bfloat1622float2(hp[t]);
            float2 fl = __bfloat1622float2(lp[t]);
            zf[2 * t] = fh.x + fl.x;
            zf[2 * t + 1] = fh.y + fl.y;
        }
    }

    unsigned long long best = ~0ull;
    const unsigned short* cl = g_cand + (size_t)n * CAP;
    for (int c = 0; c < cnt; c++) {
        int code = cl[c];
        const float4* cb = (const float4*)(g_CB + (size_t)code * 256 + lane * 8);
        float4 c0 = cb[0], c1 = cb[1];
        float d = zf[0] * c0.x + zf[1] * c0.y + zf[2] * c0.z + zf[3] * c0.w
                + zf[4] * c1.x + zf[5] * c1.y + zf[6] * c1.z + zf[7] * c1.w;
        #pragma unroll
        for (int o = 16; o; o >>= 1) d += __shfl_xor_sync(0xffffffffu, d, o);
        float sc = fmaf(-2.f, d, g_cbsq[code]);
        uint32_t fb = __float_as_uint(sc);
        uint32_t key = (fb & 0x80000000u) ? ~fb : (fb | 0x80000000u);
        unsigned long long u = ((unsigned long long)key << 32) | (unsigned)code;
        best = best < u ? best : u;
    }
    if (lane == 0) g_best[n] = best;
}

// -------- gather z_q + loss + histogram (coalesced CB rows) --------
__global__ void __launch_bounds__(256) gather_loss(const float* __restrict__ z,
                                                   float* __restrict__ out) {
    int x = blockIdx.x;
    int b = x >> 7, s0 = (x & 127) * 64;
    int t = threadIdx.x;
    int s = s0 + (t & 63);
    int d4b = t >> 6;
    int n = b * THW + s;
    int id = (int)(unsigned int)(g_best[n] & 0xffffffffull);
    if (t < 64) atomicAdd(&g_counts[id], 1);
    const float* cbrow = g_CB + (size_t)id * 256;
    size_t ebase = ((size_t)b << 21) + s;
    float lsum = 0.f;
    #pragma unroll 4
    for (int it = 0; it < 16; it++) {
        int d4 = d4b + 4 * it;
        float4 q = *(const float4*)(cbrow + d4 * 4);
        size_t e = ebase + (size_t)(d4 * 4) * THW;
        float z0 = z[e];            out[e] = q.x;
        float z1 = z[e + THW];      out[e + THW] = q.y;
        float z2 = z[e + 2 * THW];  out[e + 2 * THW] = q.z;
        float z3 = z[e + 3 * THW];  out[e + 3 * THW] = q.w;
        float d0 = q.x - z0, d1 = q.y - z1, d2 = q.z - z2, d3 = q.w - z3;
        lsum += d0 * d0 + d1 * d1 + d2 * d2 + d3 * d3;
    }
    float ls = blockReduceSum(lsum);
    if (t == 0) atomicAdd(&g_scal[2], ls);
}

// -------- finalize scalars --------
__global__ void __launch_bounds__(256) finalize(float* __restrict__ out) {
    float ps = 0.f;
    for (int k = threadIdx.x; k < KK; k += 256) {
        float e = (float)g_counts[k] * (1.f / (float)NN);
        ps += e * logf(e + 1e-10f);
    }
    float ent = blockReduceSum(ps);
    float dp = (g_zcol[threadIdx.x] * (1.f / (float)NN)) *
               (g_csum[threadIdx.x] * (1.f / (float)KK));
    float dot = blockReduceSum(dp);
    if (threadIdx.x == 0) {
        float loss = 1.25f * g_scal[2] / (float)((size_t)NN * DD);
        float perp = expf(-ent);
        float meand = g_scal[0] / (float)NN + g_scal[1] / (float)KK - 2.f * dot;
        out[4194304] = loss;
        out[4194305] = perp;
        out[4194306] = meand;
    }
}

extern "C" void kernel_launch(void* const* d_in, const int* in_sizes, int n_in,
                              void* d_out, int out_size) {
    const float* z   = (const float*)d_in[0];
    const float* emb = (const float*)d_in[1];
    const float* w1  = (const float*)d_in[2];
    const float* w2  = (const float*)d_in[3];
    float* out = (float*)d_out;

    static int attr_done = 0;
    if (!attr_done) {
        cudaFuncSetAttribute(dist_approx, cudaFuncAttributeMaxDynamicSharedMemorySize,
                             DIST_SMEM);
        attr_done = 1;
    }

    k_init<<<64, 256>>>();
    fused_pre<<<dim3(4, 128, 2), 256>>>(z, emb, w1);
    gemm_cb<<<dim3(4, 128), 256>>>(w2);
    dist_approx<<<dim3(64, 128), 256, DIST_SMEM>>>();
    refine<<<2048, 256>>>();
    gather_loss<<<256, 256>>>(z, out);
    finalize<<<1, 256>>>(out);
}